// round 13
// baseline (speedup 1.0000x reference)
#include <cuda_runtime.h>
#include <math.h>

#define BATCH 32
#define CC 256
#define CM 64
#define NX 961
#define NZ 49
#define EPSB 1e-5f
#define SPAD 976     // padded leading dim of S (16-float aligned)
#define UPAD 64      // padded K-prefix (u cols / attn^T rows)

typedef unsigned long long ull;

#define FMA_X2(d, a, b) \
    asm("fma.rn.f32x2 %0, %1, %2, %0;" : "+l"(d) : "l"(a), "l"(b))
#define PACK_DUP(d, f) \
    asm("mov.b64 %0, {%1, %1};" : "=l"(d) : "f"(f))
#define PACK2(d, flo, fhi) \
    asm("mov.b64 %0, {%1, %2};" : "=l"(d) : "f"(flo), "f"(fhi))
#define UNPACK2(flo, fhi, s) \
    asm("mov.b64 {%0, %1}, %2;" : "=f"(flo), "=f"(fhi) : "l"(s))

// ---------------- scratch (device globals; no allocation) ----------------
__device__ float g_xf_g[BATCH * CC * NX];
__device__ float g_zf_t[BATCH * CC * NZ];
__device__ float g_zf_g[BATCH * CC * NZ];
__device__ float g_tp  [BATCH * CC * NZ];    // t' = Wq^T zf_t
__device__ float g_u   [BATCH * CC * UPAD];  // u = Wfi_left zf_g (cols 49..63 = 0)
__device__ float g_r   [BATCH * NZ];
__device__ float g_sim [BATCH * NX * NZ];
__device__ float g_simT[BATCH * UPAD * NX];  // attn^T, rows 49..63 = 0
__device__ float g_gat [BATCH * CC * NX];
__device__ float g_gatT[BATCH * NX * CC];
__device__ float g_e   [BATCH * CM * NX];
__device__ float g_S   [(size_t)BATCH * NX * SPAD];
__device__ float2 g_colpk[(size_t)BATCH * NX * NX];
__device__ int   g_colcnt[BATCH * NX];

// ============ 128x128 fp32 GEMM: dup-A smem, double-buffered, concat ====
// Requires K % 16 == 0 and (ksplit < 0 or ksplit % 16 == 0).
#define GM 128
#define GN 128
#define GK 16
#define GPAD 132
#define APAD 264      // duplicated A row: 2*128 floats (+8 pad)

__global__ __launch_bounds__(256, 2)
void gemm128f_kernel(
    const float* __restrict__ A, size_t sAb, int lda,
    const float* __restrict__ A2, size_t sA2b, int lda2,
    const float* __restrict__ B, size_t sBb, int ldb,
    const float* __restrict__ B2, size_t sB2b, int ldb2,
    int ksplit,
    float* __restrict__ Cout, size_t sCb, int ldc,
    int M, int N, int K,
    const float* __restrict__ bias, int epi,
    const float* __restrict__ gamma, const float* __restrict__ beta,
    const float* __restrict__ mean,  const float* __restrict__ var)
{
    __shared__ float As2[2][GK][APAD];
    __shared__ float Bs [2][GK][GPAD];

    int b = blockIdx.z;
    const float* Ab  = A + (size_t)b * sAb;
    const float* A2b = A2 ? (A2 + (size_t)b * sA2b) : nullptr;
    const float* Bb  = B + (size_t)b * sBb;
    const float* B2b = B2 ? (B2 + (size_t)b * sB2b) : nullptr;
    float* Cb = Cout + (size_t)b * sCb;

    int m0 = blockIdx.y * GM;
    int n0 = blockIdx.x * GN;
    int tid = threadIdx.x;
    int tx = tid & 15, ty = tid >> 4;

    // hoisted mappings (k0-invariant)
    int kA = tid & 15;
    int lmA[8]; bool vA[8];
    #pragma unroll
    for (int r = 0; r < 8; r++) {
        lmA[r] = (tid >> 4) + r * 16;
        vA[r] = (m0 + lmA[r]) < M;
    }
    int nB = tid & 127;
    bool vB = (n0 + nB) < N;
    int kB0 = tid >> 7;

    ull acc2[8][4] = {};
    float pa[8], pb[8];

    auto load_tiles = [&](int k0) {
        const float* Asrc; int ald;
        const float* Bsrc; int bld;
        if (ksplit >= 0 && k0 >= ksplit) {
            Asrc = A2b + (k0 - ksplit); ald = lda2;
            Bsrc = B2b + (size_t)(k0 - ksplit) * ldb2; bld = ldb2;
        } else {
            Asrc = Ab + k0; ald = lda;
            Bsrc = Bb + (size_t)k0 * ldb; bld = ldb;
        }
        #pragma unroll
        for (int r = 0; r < 8; r++)
            pa[r] = vA[r] ? Asrc[(size_t)(m0 + lmA[r]) * ald + kA] : 0.f;
        const float* Bp = Bsrc + (size_t)kB0 * bld + (n0 + nB);
        #pragma unroll
        for (int r = 0; r < 8; r++)
            pb[r] = vB ? Bp[(size_t)(2 * r) * bld] : 0.f;
    };
    auto store_tiles = [&](int buf) {
        #pragma unroll
        for (int r = 0; r < 8; r++) {
            ull w; PACK_DUP(w, pa[r]);
            *reinterpret_cast<ull*>(&As2[buf][kA][2 * lmA[r]]) = w;
        }
        #pragma unroll
        for (int r = 0; r < 8; r++) Bs[buf][kB0 + 2 * r][nB] = pb[r];
    };
    auto compute = [&](int buf) {
        #pragma unroll
        for (int k = 0; k < GK; k++) {
            ulonglong2 A01 = *reinterpret_cast<const ulonglong2*>(&As2[buf][k][ty * 8]);
            ulonglong2 A23 = *reinterpret_cast<const ulonglong2*>(&As2[buf][k][ty * 8 + 4]);
            ulonglong2 A45 = *reinterpret_cast<const ulonglong2*>(&As2[buf][k][128 + ty * 8]);
            ulonglong2 A67 = *reinterpret_cast<const ulonglong2*>(&As2[buf][k][128 + ty * 8 + 4]);
            ulonglong2 b01 = *reinterpret_cast<const ulonglong2*>(&Bs[buf][k][tx * 4]);
            ulonglong2 b23 = *reinterpret_cast<const ulonglong2*>(&Bs[buf][k][tx * 4 + 64]);
            ull ap[8] = {A01.x, A01.y, A23.x, A23.y, A45.x, A45.y, A67.x, A67.y};
            ull bp[4] = {b01.x, b01.y, b23.x, b23.y};
            #pragma unroll
            for (int i = 0; i < 8; i++)
                #pragma unroll
                for (int jp = 0; jp < 4; jp++)
                    FMA_X2(acc2[i][jp], ap[i], bp[jp]);
        }
    };

    load_tiles(0);
    store_tiles(0);
    __syncthreads();

    int nk = K / GK;
    for (int it = 0; it < nk; it++) {
        bool more = (it + 1) < nk;
        if (more) load_tiles((it + 1) * GK);
        compute(it & 1);
        if (more) { store_tiles((it + 1) & 1); __syncthreads(); }
    }

    #pragma unroll
    for (int i = 0; i < 8; i++) {
        int m = m0 + ty * 4 + (i & 3) + ((i >> 2) << 6);
        if (m >= M) continue;
        float bval = bias ? bias[m] : 0.f;
        float s = 1.f, sh = 0.f;
        if (epi == 1) {
            s = gamma[m] * rsqrtf(var[m] + EPSB);
            sh = beta[m] - mean[m] * s;
        }
        #pragma unroll
        for (int jp = 0; jp < 4; jp++) {
            float vlo, vhi;
            UNPACK2(vlo, vhi, acc2[i][jp]);
            float vv[2] = {vlo, vhi};
            #pragma unroll
            for (int h = 0; h < 2; h++) {
                int n = n0 + tx * 4 + ((jp & 1) << 1) + h + ((jp >> 1) << 6);
                if (n >= N) continue;
                float v = vv[h] + bval;
                if (epi == 1) v = fmaxf(v * s + sh, 0.f);
                Cb[(size_t)m * ldc + n] = v;
            }
        }
    }
}

// ============ symmetric S = e^T e, dup-A, double-buffered, mirror ============
__global__ __launch_bounds__(256, 2)
void gemm_symL_kernel(const float* __restrict__ e, float* __restrict__ S)
{
    __shared__ float As2[2][GK][APAD];
    __shared__ float Bs [2][GK][GPAD];

    int b = blockIdx.z;
    const float* E = e + (size_t)b * CM * NX;
    float* Sb = S + (size_t)b * NX * SPAD;

    int lin = blockIdx.x, i = 0;
    while (lin >= 8 - i) { lin -= 8 - i; i++; }
    int j = i + lin;
    int m0 = i * 128, n0 = j * 128;

    int tid = threadIdx.x, tx = tid & 15, ty = tid >> 4;
    int mn = tid & 127;
    int kk = tid >> 7;
    bool vA = (m0 + mn) < NX;
    bool vB = (n0 + mn) < NX;

    ull acc2[8][4] = {};
    float pa[8], pb[8];

    auto load_tiles = [&](int k0) {
        const float* Ea = E + (size_t)(k0 + kk) * NX;
        #pragma unroll
        for (int r = 0; r < 8; r++) {
            const float* Er = Ea + (size_t)(2 * r) * NX;
            pa[r] = vA ? Er[m0 + mn] : 0.f;
            pb[r] = vB ? Er[n0 + mn] : 0.f;
        }
    };
    auto store_tiles = [&](int buf) {
        #pragma unroll
        for (int r = 0; r < 8; r++) {
            ull w; PACK_DUP(w, pa[r]);
            *reinterpret_cast<ull*>(&As2[buf][kk + 2 * r][2 * mn]) = w;
            Bs[buf][kk + 2 * r][mn] = pb[r];
        }
    };
    auto compute = [&](int buf) {
        #pragma unroll
        for (int k = 0; k < GK; k++) {
            ulonglong2 A01 = *reinterpret_cast<const ulonglong2*>(&As2[buf][k][ty * 8]);
            ulonglong2 A23 = *reinterpret_cast<const ulonglong2*>(&As2[buf][k][ty * 8 + 4]);
            ulonglong2 A45 = *reinterpret_cast<const ulonglong2*>(&As2[buf][k][128 + ty * 8]);
            ulonglong2 A67 = *reinterpret_cast<const ulonglong2*>(&As2[buf][k][128 + ty * 8 + 4]);
            ulonglong2 b01 = *reinterpret_cast<const ulonglong2*>(&Bs[buf][k][tx * 4]);
            ulonglong2 b23 = *reinterpret_cast<const ulonglong2*>(&Bs[buf][k][tx * 4 + 64]);
            ull ap[8] = {A01.x, A01.y, A23.x, A23.y, A45.x, A45.y, A67.x, A67.y};
            ull bp[4] = {b01.x, b01.y, b23.x, b23.y};
            #pragma unroll
            for (int ii = 0; ii < 8; ii++)
                #pragma unroll
                for (int jp = 0; jp < 4; jp++)
                    FMA_X2(acc2[ii][jp], ap[ii], bp[jp]);
        }
    };

    load_tiles(0);
    store_tiles(0);
    __syncthreads();

    const int nk = CM / GK;   // 4
    for (int it = 0; it < nk; it++) {
        bool more = (it + 1) < nk;
        if (more) load_tiles((it + 1) * GK);
        compute(it & 1);
        if (more) { store_tiles((it + 1) & 1); __syncthreads(); }
    }

    float acc[8][8];
    #pragma unroll
    for (int ii = 0; ii < 8; ii++)
        #pragma unroll
        for (int jp = 0; jp < 4; jp++)
            UNPACK2(acc[ii][jp * 2], acc[ii][jp * 2 + 1], acc2[ii][jp]);

    #pragma unroll
    for (int ii = 0; ii < 8; ii++) {
        int m = m0 + ty * 4 + (ii & 3) + ((ii >> 2) << 6);
        if (m >= NX) continue;
        #pragma unroll
        for (int jp = 0; jp < 4; jp++)
            #pragma unroll
            for (int h = 0; h < 2; h++) {
                int n = n0 + tx * 4 + ((jp & 1) << 1) + h + ((jp >> 1) << 6);
                if (n < NX) Sb[(size_t)m * SPAD + n] = acc[ii][jp * 2 + h];
            }
    }
    if (i != j) {
        #pragma unroll
        for (int jp = 0; jp < 4; jp++)
            #pragma unroll
            for (int h = 0; h < 2; h++) {
                int n = n0 + tx * 4 + ((jp & 1) << 1) + h + ((jp >> 1) << 6);
                if (n >= NX) continue;
                float4 v0 = make_float4(acc[0][jp * 2 + h], acc[1][jp * 2 + h],
                                        acc[2][jp * 2 + h], acc[3][jp * 2 + h]);
                float4 v1 = make_float4(acc[4][jp * 2 + h], acc[5][jp * 2 + h],
                                        acc[6][jp * 2 + h], acc[7][jp * 2 + h]);
                *reinterpret_cast<float4*>(&Sb[(size_t)n * SPAD + m0 + ty * 4]) = v0;
                *reinterpret_cast<float4*>(&Sb[(size_t)n * SPAD + m0 + 64 + ty * 4]) = v1;
            }
    }
}

// ================= small GEMM: 32x64 tile, 128 threads =======
struct SmTask {
    const float* A; size_t sAb; int lda; int aT;
    const float* B; size_t sBb; int ldb;
    float* C; size_t sCb; int ldc;
    int M, N, K, Npad;
    const float* bias; int epi;
    const float* gamma; const float* beta; const float* mean; const float* var;
    const float* cb; size_t scb;
};

#define SBK 16
__global__ __launch_bounds__(128)
void gemm_sm_dual(SmTask t0, SmTask t1, int split)
{
    int by = blockIdx.y;
    bool second = (split > 0 && by >= split);
    const SmTask& t = second ? t1 : t0;
    int mt = second ? by - split : by;

    int b = blockIdx.z;
    const float* Ab = t.A + (size_t)b * t.sAb;
    const float* Bb = t.B + (size_t)b * t.sBb;
    float* Cb = t.C + (size_t)b * t.sCb;

    __shared__ float As[SBK][32];
    __shared__ float Bs[SBK][64];

    int tid = threadIdx.x;
    int tx = tid & 15, ty = tid >> 4;
    int m0 = mt * 32;

    ull acc2[4][2] = {};

    for (int k0 = 0; k0 < t.K; k0 += SBK) {
        if (!t.aT) {
            #pragma unroll
            for (int r = 0; r < 4; r++) {
                int idx = tid + r * 128;
                int tk = idx & 15, tm = idx >> 4;
                int gm = m0 + tm, gk = k0 + tk;
                As[tk][tm] = (gm < t.M && gk < t.K) ? Ab[(size_t)gm * t.lda + gk] : 0.f;
            }
        } else {
            #pragma unroll
            for (int r = 0; r < 4; r++) {
                int idx = tid + r * 128;
                int tm = idx & 31, tk = idx >> 5;
                int gm = m0 + tm, gk = k0 + tk;
                As[tk][tm] = (gm < t.M && gk < t.K) ? Ab[(size_t)gk * t.lda + gm] : 0.f;
            }
        }
        #pragma unroll
        for (int r = 0; r < 8; r++) {
            int idx = tid + r * 128;
            int tn = idx & 63, tk = idx >> 6;
            int gk = k0 + tk;
            Bs[tk][tn] = (tn < t.N && gk < t.K) ? Bb[(size_t)gk * t.ldb + tn] : 0.f;
        }
        __syncthreads();

        #pragma unroll
        for (int k = 0; k < SBK; k++) {
            float4 av = *reinterpret_cast<const float4*>(&As[k][ty * 4]);
            ulonglong2 bv = *reinterpret_cast<const ulonglong2*>(&Bs[k][tx * 4]);
            float a4[4] = {av.x, av.y, av.z, av.w};
            ull bp[2] = {bv.x, bv.y};
            #pragma unroll
            for (int i = 0; i < 4; i++) {
                ull ap;
                PACK_DUP(ap, a4[i]);
                #pragma unroll
                for (int jp = 0; jp < 2; jp++)
                    FMA_X2(acc2[i][jp], ap, bp[jp]);
            }
        }
        __syncthreads();
    }

    #pragma unroll
    for (int i = 0; i < 4; i++) {
        int m = m0 + ty * 4 + i;
        if (m >= t.M) continue;
        float bval = t.bias ? t.bias[m] : 0.f;
        float s = 1.f, sh = 0.f;
        if (t.epi == 1) {
            s = t.gamma[m] * rsqrtf(t.var[m] + EPSB);
            sh = t.beta[m] - t.mean[m] * s;
        }
        #pragma unroll
        for (int jp = 0; jp < 2; jp++) {
            float vlo, vhi;
            UNPACK2(vlo, vhi, acc2[i][jp]);
            float vv[2] = {vlo, vhi};
            #pragma unroll
            for (int h = 0; h < 2; h++) {
                int n = tx * 4 + jp * 2 + h;
                if (n >= t.Npad) continue;
                float v;
                if (n >= t.N) {
                    v = 0.f;
                } else {
                    v = vv[h] + bval;
                    if (t.epi == 1)      v = fmaxf(v * s + sh, 0.f);
                    else if (t.epi == 3) v += t.cb[(size_t)b * t.scb + n];
                }
                Cb[(size_t)m * t.ldc + n] = v;
            }
        }
    }
}

// ---------------- r[b][m] = bq . zf_t[b][:,m] ----------------
__global__ void rvec_kernel(const float* __restrict__ zf_t,
                            const float* __restrict__ bq,
                            float* __restrict__ r)
{
    int b = blockIdx.x;
    int m = threadIdx.x;
    if (m >= NZ) return;
    const float* z = zf_t + (size_t)b * CC * NZ;
    float acc = 0.f;
    for (int c = 0; c < CC; c++)
        acc += bq[c] * z[(size_t)c * NZ + m];
    r[b * NZ + m] = acc;
}

// ---- softmax over last dim (49); writes attn^T (rows 49..63 zeroed) ----
__global__ void softmax49_kernel(float* __restrict__ S, float* __restrict__ ST,
                                 int rows)
{
    int warp = (blockIdx.x * blockDim.x + threadIdx.x) >> 5;
    int lane = threadIdx.x & 31;
    if (warp >= rows) return;
    float* row = S + (size_t)warp * NZ;
    int b = warp / NX;
    int n = warp - b * NX;
    float v0 = row[lane];
    float v1 = (lane + 32 < NZ) ? row[lane + 32] : -INFINITY;
    float mx = fmaxf(v0, v1);
    #pragma unroll
    for (int o = 16; o; o >>= 1) mx = fmaxf(mx, __shfl_xor_sync(0xFFFFFFFFu, mx, o));
    float e0 = expf(v0 - mx);
    float e1 = (lane + 32 < NZ) ? expf(v1 - mx) : 0.f;
    float sm = e0 + e1;
    #pragma unroll
    for (int o = 16; o; o >>= 1) sm += __shfl_xor_sync(0xFFFFFFFFu, sm, o);
    float inv = 1.f / sm;
    float* STb = ST + (size_t)b * UPAD * NX;
    STb[(size_t)lane * NX + n] = e0 * inv;
    STb[(size_t)(lane + 32) * NX + n] = (lane + 32 < NZ) ? e1 * inv : 0.f;
}

// ---------------- conv3x3 + BN + PReLU (FFMA2, OCB=8) --------
#define CI 8
#define OCB 8
#define PW 33

__global__ __launch_bounds__(256, 2)
void conv3_kernel(const float* __restrict__ gat, const float* __restrict__ Wm,
                  const float* __restrict__ bm,
                  const float* __restrict__ mg, const float* __restrict__ mb,
                  const float* __restrict__ mm, const float* __restrict__ mv,
                  const float* __restrict__ pa,
                  float* __restrict__ e)
{
    int b = blockIdx.x;
    int ocg = blockIdx.y;
    __shared__ float in_s[CI][PW * PW];
    __shared__ ull   w2_s[OCB][CI][9];
    int tid = threadIdx.x;

    for (int idx = tid; idx < CI * PW * PW; idx += 256)
        (&in_s[0][0])[idx] = 0.f;
    __syncthreads();

    int y  = tid >> 3;
    int x0 = (tid & 7) << 2;
    bool active = (tid < 248);

    ull acc2[OCB][2] = {};
    const float* gb = gat + (size_t)b * CC * NX;

    for (int c0 = 0; c0 < CC; c0 += CI) {
        for (int idx = tid; idx < CI * NX; idx += 256) {
            int c = idx / NX, p = idx - c * NX;
            int yy = p / 31, xx = p - yy * 31;
            in_s[c][(yy + 1) * PW + (xx + 1)] = gb[(size_t)(c0 + c) * NX + p];
        }
        for (int idx = tid; idx < OCB * CI * 9; idx += 256) {
            int o = idx / (CI * 9), rem = idx % (CI * 9);
            int c = rem / 9, k = rem % 9;
            float w = Wm[((size_t)(ocg * OCB + o) * CC + (c0 + c)) * 9 + k];
            ull wp; PACK_DUP(wp, w);
            w2_s[o][c][k] = wp;
        }
        __syncthreads();

        if (active) {
            #pragma unroll
            for (int c = 0; c < CI; c++) {
                float nb[3][6];
                #pragma unroll
                for (int dy = 0; dy < 3; dy++)
                    #pragma unroll
                    for (int dx = 0; dx < 6; dx++)
                        nb[dy][dx] = (x0 + dx <= PW - 1)
                                   ? in_s[c][(y + dy) * PW + (x0 + dx)] : 0.f;
                ull nb2[3][3][2];
                #pragma unroll
                for (int dy = 0; dy < 3; dy++)
                    #pragma unroll
                    for (int dx = 0; dx < 3; dx++) {
                        PACK2(nb2[dy][dx][0], nb[dy][dx + 0], nb[dy][dx + 1]);
                        PACK2(nb2[dy][dx][1], nb[dy][dx + 2], nb[dy][dx + 3]);
                    }
                #pragma unroll
                for (int o = 0; o < OCB; o++) {
                    #pragma unroll
                    for (int dy = 0; dy < 3; dy++)
                        #pragma unroll
                        for (int dx = 0; dx < 3; dx++) {
                            ull wp = w2_s[o][c][dy * 3 + dx];
                            FMA_X2(acc2[o][0], nb2[dy][dx][0], wp);
                            FMA_X2(acc2[o][1], nb2[dy][dx][1], wp);
                        }
                }
            }
        }
        __syncthreads();
    }

    if (active) {
        float a = pa[0];
        #pragma unroll
        for (int o = 0; o < OCB; o++) {
            int oc = ocg * OCB + o;
            float s = mg[oc] * rsqrtf(mv[oc] + EPSB);
            float sh = mb[oc] - mm[oc] * s;
            float av[4];
            UNPACK2(av[0], av[1], acc2[o][0]);
            UNPACK2(av[2], av[3], acc2[o][1]);
            #pragma unroll
            for (int p = 0; p < 4; p++) {
                int x = x0 + p;
                if (x < 31) {
                    float v = (av[p] + bm[oc]) * s + sh;
                    v = (v >= 0.f) ? v : a * v;
                    e[(size_t)b * CM * NX + (size_t)oc * NX + (y * 31 + x)] = v;
                }
            }
        }
    }
}

// ---- tiled transpose gat->gatT; blocks (z==0,y==0) also zero colcnt ----
__global__ void transpose_kernel(const float* __restrict__ in, float* __restrict__ outT,
                                 int* __restrict__ cnt)
{
    __shared__ float tile[32][33];
    int b = blockIdx.z;
    int n0 = blockIdx.x * 32;
    int c0 = blockIdx.y * 32;
    int lx = threadIdx.x, ly = threadIdx.y;
    if (blockIdx.z == 0 && blockIdx.y == 0) {
        int base = blockIdx.x * 256 + ly * 32 + lx;
        for (int i = base; i < BATCH * NX; i += 31 * 256) cnt[i] = 0;
    }
    #pragma unroll
    for (int r = 0; r < 4; r++) {
        int c = c0 + ly + r * 8, n = n0 + lx;
        if (n < NX) tile[ly + r * 8][lx] = in[((size_t)b * CC + c) * NX + n];
    }
    __syncthreads();
    #pragma unroll
    for (int r = 0; r < 4; r++) {
        int n = n0 + ly + r * 8, c = c0 + lx;
        if (n < NX) outT[((size_t)b * NX + n) * CC + c] = tile[lx][ly + r * 8];
    }
}

// ---------------- sparsemax + scatter nonzeros to packed column lists ------
__global__ void sparsemax_scatter_kernel(const float* __restrict__ S,
                                         float2* __restrict__ colpk,
                                         int*    __restrict__ colcnt,
                                         int rows)
{
    int warp = (blockIdx.x * blockDim.x + threadIdx.x) >> 5;
    int lane = threadIdx.x & 31;
    if (warp >= rows) return;
    const float* row = S + (size_t)warp * SPAD;
    int b = warp / NX;
    int n = warp - b * NX;

    float v[31];
    #pragma unroll
    for (int t = 0; t < 31; t++) {
        int idx = lane + 32 * t;
        v[t] = (idx < NX) ? row[idx] : -INFINITY;
    }
    float mx = -INFINITY;
    #pragma unroll
    for (int t = 0; t < 31; t++) mx = fmaxf(mx, v[t]);
    #pragma unroll
    for (int o = 16; o; o >>= 1) mx = fmaxf(mx, __shfl_xor_sync(0xFFFFFFFFu, mx, o));
    #pragma unroll
    for (int t = 0; t < 31; t++) v[t] -= mx;

    float lo = -1.f, hi = 0.f;
    for (int it = 0; it < 26; it++) {
        float mid = 0.5f * (lo + hi);
        float f = 0.f;
        #pragma unroll
        for (int t = 0; t < 31; t++) f += fmaxf(v[t] - mid, 0.f);
        #pragma unroll
        for (int o = 16; o; o >>= 1) f += __shfl_xor_sync(0xFFFFFFFFu, f, o);
        if (f >= 1.f) lo = mid; else hi = mid;
    }
    float tm = 0.5f * (lo + hi);
    float cnt = 0.f, sm = 0.f;
    #pragma unroll
    for (int t = 0; t < 31; t++) {
        if (v[t] > tm) { cnt += 1.f; sm += v[t]; }
    }
    #pragma unroll
    for (int o = 16; o; o >>= 1) {
        cnt += __shfl_xor_sync(0xFFFFFFFFu, cnt, o);
        sm  += __shfl_xor_sync(0xFFFFFFFFu, sm,  o);
    }
    float tau = (sm - 1.f) / cnt;

    #pragma unroll
    for (int t = 0; t < 31; t++) {
        int idx = lane + 32 * t;
        if (idx < NX) {
            float p = v[t] - tau;
            if (p > 0.f) {
                int col = b * NX + idx;
                int slot = atomicAdd(&colcnt[col], 1);
                colpk[(size_t)col * NX + slot] = make_float2(p, __int_as_float(n));
            }
        }
    }
}

// ---- sparse out: out[b,:,m] = gat[b,:,m] + sum_n p * gat[b,:,n] ----
#define MCOLS 32
__global__ __launch_bounds__(256, 4)
void sparse_out_kernel(const float* __restrict__ gatT,
                       const float2* __restrict__ colpk,
                       const int*    __restrict__ colcnt,
                       float* __restrict__ out)
{
    int b  = blockIdx.y;
    int m0 = blockIdx.x * MCOLS;
    int tid = threadIdx.x;
    __shared__ float accs[MCOLS][257];

    const float* gT = gatT + (size_t)b * NX * CC;

    for (int mi = 0; mi < MCOLS; mi++) {
        int m = m0 + mi;
        if (m >= NX) break;
        float acc = gT[(size_t)m * CC + tid];
        int cnt = colcnt[b * NX + m];
        const float2* pk = colpk + (size_t)(b * NX + m) * NX;
        int s = 0;
        for (; s + 4 <= cnt; s += 4) {
            float2 q0 = pk[s], q1 = pk[s + 1], q2 = pk[s + 2], q3 = pk[s + 3];
            float v0 = gT[(size_t)__float_as_int(q0.y) * CC + tid];
            float v1 = gT[(size_t)__float_as_int(q1.y) * CC + tid];
            float v2 = gT[(size_t)__float_as_int(q2.y) * CC + tid];
            float v3 = gT[(size_t)__float_as_int(q3.y) * CC + tid];
            acc += q0.x * v0;
            acc += q1.x * v1;
            acc += q2.x * v2;
            acc += q3.x * v3;
        }
        for (; s < cnt; s++) {
            float2 q = pk[s];
            acc += q.x * gT[(size_t)__float_as_int(q.y) * CC + tid];
        }
        accs[mi][tid] = acc;
    }
    __syncthreads();

    #pragma unroll
    for (int r = 0; r < MCOLS; r++) {
        int idx = tid + r * 256;
        int c = idx >> 5, mi = idx & 31;
        int m = m0 + mi;
        if (m < NX)
            out[((size_t)b * CC + c) * NX + m] = accs[mi][c];
    }
}

// ---------------- launch ----------------
extern "C" void kernel_launch(void* const* d_in, const int* in_sizes, int n_in,
                              void* d_out, int out_size)
{
    const float* zf  = (const float*)d_in[0];
    const float* xf  = (const float*)d_in[1];
    const float* Wq  = (const float*)d_in[2];
    const float* bq  = (const float*)d_in[3];
    const float* Ws  = (const float*)d_in[4];
    const float* bs  = (const float*)d_in[5];
    const float* Wg  = (const float*)d_in[6];
    const float* bg  = (const float*)d_in[7];
    const float* g_gamma = (const float*)d_in[8];
    const float* g_beta  = (const float*)d_in[9];
    const float* g_mean  = (const float*)d_in[10];
    const float* g_var   = (const float*)d_in[11];
    const float* Wfi = (const float*)d_in[12];
    const float* bfi = (const float*)d_in[13];
    const float* fi_gamma = (const float*)d_in[14];
    const float* fi_beta  = (const float*)d_in[15];
    const float* fi_mean  = (const float*)d_in[16];
    const float* fi_var   = (const float*)d_in[17];
    const float* Wm  = (const float*)d_in[18];
    const float* bm  = (const float*)d_in[19];
    const float* m_gamma = (const float*)d_in[20];
    const float* m_beta  = (const float*)d_in[21];
    const float* m_mean  = (const float*)d_in[22];
    const float* m_var   = (const float*)d_in[23];
    const float* prelu_a = (const float*)d_in[24];
    float* out = (float*)d_out;

    float *xf_g, *zf_t, *zf_g, *tp, *u, *r, *sim, *simT, *gat, *gatT, *e, *S;
    float2 *colpk; int *colcnt;
    cudaGetSymbolAddress((void**)&xf_g, g_xf_g);
    cudaGetSymbolAddress((void**)&zf_t, g_zf_t);
    cudaGetSymbolAddress((void**)&zf_g, g_zf_g);
    cudaGetSymbolAddress((void**)&tp,   g_tp);
    cudaGetSymbolAddress((void**)&u,    g_u);
    cudaGetSymbolAddress((void**)&r,    g_r);
    cudaGetSymbolAddress((void**)&sim,  g_sim);
    cudaGetSymbolAddress((void**)&simT, g_simT);
    cudaGetSymbolAddress((void**)&gat,  g_gat);
    cudaGetSymbolAddress((void**)&gatT, g_gatT);
    cudaGetSymbolAddress((void**)&e,    g_e);
    cudaGetSymbolAddress((void**)&S,    g_S);
    cudaGetSymbolAddress((void**)&colpk, g_colpk);
    cudaGetSymbolAddress((void**)&colcnt, g_colcnt);

    dim3 blk(256);
    const size_t sX  = (size_t)CC * NX;
    const size_t sZ  = (size_t)CC * NZ;
    const size_t sU  = (size_t)CC * UPAD;
    const size_t sSim = (size_t)NX * NZ;
    const size_t sST = (size_t)UPAD * NX;

    SmTask tA = { Ws, 0, CC, 0,  zf, sZ, NZ,  zf_t, sZ, NZ,  CC, NZ, CC, NZ,
                  bs, 0,  nullptr, nullptr, nullptr, nullptr,  nullptr, 0 };
    SmTask tB = { Wg, 0, CC, 0,  zf, sZ, NZ,  zf_g, sZ, NZ,  CC, NZ, CC, NZ,
                  bg, 1,  g_gamma, g_beta, g_mean, g_var,  nullptr, 0 };
    SmTask tD = { Wq, 0, CC, 1,  zf_t, sZ, NZ,  tp, sZ, NZ,  CC, NZ, CC, NZ,
                  nullptr, 0,  nullptr, nullptr, nullptr, nullptr,  nullptr, 0 };
    SmTask tE = { Wfi, 0, 2 * CC, 0,  zf_g, sZ, NZ,  u, sU, UPAD,  CC, NZ, CC, UPAD,
                  nullptr, 0,  nullptr, nullptr, nullptr, nullptr,  nullptr, 0 };
    SmTask tG = { xf, sX, NX, 1,  tp, sZ, NZ,  sim, sSim, NZ,  NX, NZ, CC, NZ,
                  nullptr, 3,  nullptr, nullptr, nullptr, nullptr,  r, NZ };

    // A+B) zf_t and zf_g
    gemm_sm_dual<<<dim3(1, 16, BATCH), 128>>>(tA, tB, 8);
    // C) r
    rvec_kernel<<<BATCH, 64>>>(zf_t, bq, r);
    // D+E) t' and u (u zero-padded to 64 cols)
    gemm_sm_dual<<<dim3(1, 16, BATCH), 128>>>(tD, tE, 8);
    // F) xf_g = relu(bn(Wg * xf + bg))
    gemm128f_kernel<<<dim3(8, 2, BATCH), blk>>>(
        Wg, 0, CC,  nullptr, 0, 0,
        xf, sX, NX,  nullptr, 0, 0,  -1,
        xf_g, sX, NX,  CC, NX, CC,  bg, 1,
        g_gamma, g_beta, g_mean, g_var);
    // G) sim = xf^T t' + r
    gemm_sm_dual<<<dim3(1, 31, BATCH), 128>>>(tG, tG, 0);
    // H) softmax -> attn^T (rows 49..63 zeroed)
    softmax49_kernel<<<(BATCH * NX + 7) / 8, blk>>>(sim, simT, BATCH * NX);
    // I) gat = relu(bn([u|Wfi_R]*[attn^T; xf_g] + bfi)), K=320, ksplit=64
    gemm128f_kernel<<<dim3(8, 2, BATCH), blk>>>(
        u, sU, UPAD,  Wfi + CC, 0, 2 * CC,
        simT, sST, NX,  xf_g, sX, NX,  UPAD,
        gat, sX, NX,  CC, NX, UPAD + CC,  bfi, 1,
        fi_gamma, fi_beta, fi_mean, fi_var);
    // J) gatT = transpose(gat); zero colcnt
    transpose_kernel<<<dim3(31, 8, BATCH), dim3(32, 8)>>>(gat, gatT, colcnt);
    // K) e = prelu(bn(conv3x3(gat) + bm))
    conv3_kernel<<<dim3(BATCH, CM / OCB), blk>>>(
        gat, Wm, bm, m_gamma, m_beta, m_mean, m_var, prelu_a, e);
    // L) S = e^T e, symmetric (36 upper-triangle tile pairs + mirror)
    gemm_symL_kernel<<<dim3(36, 1, BATCH), blk>>>(e, S);
    // M) sparsemax rows of S -> packed sparse column lists
    sparsemax_scatter_kernel<<<(BATCH * NX + 7) / 8, blk>>>(
        S, colpk, colcnt, BATCH * NX);
    // N) out = gat + gat * P (sparse)
    sparse_out_kernel<<<dim3((NX + MCOLS - 1) / MCOLS, BATCH), blk>>>(
        gatT, colpk, colcnt, out);
}

// round 14
// speedup vs baseline: 1.0499x; 1.0499x over previous
#include <cuda_runtime.h>
#include <math.h>

#define BATCH 32
#define CC 256
#define CM 64
#define NX 961
#define NZ 49
#define EPSB 1e-5f
#define SPAD 976     // padded leading dim of S (16-float aligned)
#define UPAD 64      // padded K-prefix (u cols / attn^T rows)

typedef unsigned long long ull;

#define FMA_X2(d, a, b) \
    asm("fma.rn.f32x2 %0, %1, %2, %0;" : "+l"(d) : "l"(a), "l"(b))
#define PACK_DUP(d, f) \
    asm("mov.b64 %0, {%1, %1};" : "=l"(d) : "f"(f))
#define PACK2(d, flo, fhi) \
    asm("mov.b64 %0, {%1, %2};" : "=l"(d) : "f"(flo), "f"(fhi))
#define UNPACK2(flo, fhi, s) \
    asm("mov.b64 {%0, %1}, %2;" : "=f"(flo), "=f"(fhi) : "l"(s))

// ---------------- scratch (device globals; no allocation) ----------------
__device__ float g_xf_g[BATCH * CC * NX];
__device__ float g_zf_t[BATCH * CC * NZ];
__device__ float g_zf_g[BATCH * CC * NZ];
__device__ float g_tp  [BATCH * CC * NZ];    // t' = Wq^T zf_t
__device__ float g_u   [BATCH * CC * UPAD];  // u = Wfi_left zf_g (cols 49..63 = 0)
__device__ float g_r   [BATCH * NZ];
__device__ float g_sim [BATCH * NX * NZ];
__device__ float g_simT[BATCH * UPAD * NX];  // attn^T, rows 49..63 = 0
__device__ float g_gat [BATCH * CC * NX];
__device__ float g_gatT[BATCH * NX * CC];
__device__ float g_e   [BATCH * CM * NX];
__device__ float g_S   [(size_t)BATCH * NX * SPAD];
__device__ float2 g_colpk[(size_t)BATCH * NX * NX];
__device__ int   g_colcnt[BATCH * NX];

// ============ 128x128 fp32 GEMM: R12 layout + double-buffered smem ====
// Requires K % 16 == 0 and (ksplit < 0 or ksplit % 16 == 0).
#define GM 128
#define GN 128
#define GK 16
#define GPAD 132

__global__ __launch_bounds__(256, 2)
void gemm128f_kernel(
    const float* __restrict__ A, size_t sAb, int lda,
    const float* __restrict__ A2, size_t sA2b, int lda2,
    const float* __restrict__ B, size_t sBb, int ldb,
    const float* __restrict__ B2, size_t sB2b, int ldb2,
    int ksplit,
    float* __restrict__ Cout, size_t sCb, int ldc,
    int M, int N, int K,
    const float* __restrict__ bias, int epi,
    const float* __restrict__ gamma, const float* __restrict__ beta,
    const float* __restrict__ mean,  const float* __restrict__ var)
{
    __shared__ float As[2][GK][GPAD];
    __shared__ float Bs[2][GK][GPAD];

    int b = blockIdx.z;
    const float* Ab  = A + (size_t)b * sAb;
    const float* A2b = A2 ? (A2 + (size_t)b * sA2b) : nullptr;
    const float* Bb  = B + (size_t)b * sBb;
    const float* B2b = B2 ? (B2 + (size_t)b * sB2b) : nullptr;
    float* Cb = Cout + (size_t)b * sCb;

    int m0 = blockIdx.y * GM;
    int n0 = blockIdx.x * GN;
    int tid = threadIdx.x;
    int tx = tid & 15, ty = tid >> 4;

    // hoisted mappings (k0-invariant)
    int kA = tid & 15;
    int lmA[8]; bool vA[8];
    #pragma unroll
    for (int r = 0; r < 8; r++) {
        lmA[r] = (tid >> 4) + r * 16;
        vA[r] = (m0 + lmA[r]) < M;
    }
    int nB = tid & 127;
    bool vB = (n0 + nB) < N;
    int kB0 = tid >> 7;

    ull acc2[8][4] = {};
    float pa[8], pb[8];

    auto load_tiles = [&](int k0) {
        const float* Asrc; int ald;
        const float* Bsrc; int bld;
        if (ksplit >= 0 && k0 >= ksplit) {
            Asrc = A2b + (k0 - ksplit); ald = lda2;
            Bsrc = B2b + (size_t)(k0 - ksplit) * ldb2; bld = ldb2;
        } else {
            Asrc = Ab + k0; ald = lda;
            Bsrc = Bb + (size_t)k0 * ldb; bld = ldb;
        }
        #pragma unroll
        for (int r = 0; r < 8; r++)
            pa[r] = vA[r] ? Asrc[(size_t)(m0 + lmA[r]) * ald + kA] : 0.f;
        const float* Bp = Bsrc + (size_t)kB0 * bld + (n0 + nB);
        #pragma unroll
        for (int r = 0; r < 8; r++)
            pb[r] = vB ? Bp[(size_t)(2 * r) * bld] : 0.f;
    };
    auto store_tiles = [&](int buf) {
        #pragma unroll
        for (int r = 0; r < 8; r++) As[buf][kA][lmA[r]] = pa[r];
        #pragma unroll
        for (int r = 0; r < 8; r++) Bs[buf][kB0 + 2 * r][nB] = pb[r];
    };
    auto compute = [&](int buf) {
        #pragma unroll
        for (int k = 0; k < GK; k++) {
            float4 a0 = *reinterpret_cast<const float4*>(&As[buf][k][ty * 4]);
            float4 a1 = *reinterpret_cast<const float4*>(&As[buf][k][ty * 4 + 64]);
            ulonglong2 b01 = *reinterpret_cast<const ulonglong2*>(&Bs[buf][k][tx * 4]);
            ulonglong2 b23 = *reinterpret_cast<const ulonglong2*>(&Bs[buf][k][tx * 4 + 64]);
            float am[8] = {a0.x, a0.y, a0.z, a0.w, a1.x, a1.y, a1.z, a1.w};
            ull bp[4] = {b01.x, b01.y, b23.x, b23.y};
            #pragma unroll
            for (int i = 0; i < 8; i++) {
                ull ap;
                PACK_DUP(ap, am[i]);
                #pragma unroll
                for (int jp = 0; jp < 4; jp++)
                    FMA_X2(acc2[i][jp], ap, bp[jp]);
            }
        }
    };

    load_tiles(0);
    store_tiles(0);
    __syncthreads();

    int nk = K / GK;
    for (int it = 0; it < nk; it++) {
        bool more = (it + 1) < nk;
        if (more) load_tiles((it + 1) * GK);
        compute(it & 1);
        if (more) { store_tiles((it + 1) & 1); __syncthreads(); }
    }

    #pragma unroll
    for (int i = 0; i < 8; i++) {
        int m = m0 + ty * 4 + (i & 3) + ((i >> 2) << 6);
        if (m >= M) continue;
        float bval = bias ? bias[m] : 0.f;
        float s = 1.f, sh = 0.f;
        if (epi == 1) {
            s = gamma[m] * rsqrtf(var[m] + EPSB);
            sh = beta[m] - mean[m] * s;
        }
        #pragma unroll
        for (int jp = 0; jp < 4; jp++) {
            float vlo, vhi;
            UNPACK2(vlo, vhi, acc2[i][jp]);
            float vv[2] = {vlo, vhi};
            #pragma unroll
            for (int h = 0; h < 2; h++) {
                int n = n0 + tx * 4 + ((jp & 1) << 1) + h + ((jp >> 1) << 6);
                if (n >= N) continue;
                float v = vv[h] + bval;
                if (epi == 1) v = fmaxf(v * s + sh, 0.f);
                Cb[(size_t)m * ldc + n] = v;
            }
        }
    }
}

// ============ symmetric S = e^T e: R12 layout + double-buffered smem ========
__global__ __launch_bounds__(256, 2)
void gemm_symL_kernel(const float* __restrict__ e, float* __restrict__ S)
{
    __shared__ float As[2][GK][GPAD];
    __shared__ float Bs[2][GK][GPAD];

    int b = blockIdx.z;
    const float* E = e + (size_t)b * CM * NX;
    float* Sb = S + (size_t)b * NX * SPAD;

    int lin = blockIdx.x, i = 0;
    while (lin >= 8 - i) { lin -= 8 - i; i++; }
    int j = i + lin;
    int m0 = i * 128, n0 = j * 128;

    int tid = threadIdx.x, tx = tid & 15, ty = tid >> 4;
    int mn = tid & 127;
    int kk = tid >> 7;
    bool vA = (m0 + mn) < NX;
    bool vB = (n0 + mn) < NX;

    ull acc2[8][4] = {};
    float pa[8], pb[8];

    auto load_tiles = [&](int k0) {
        const float* Ea = E + (size_t)(k0 + kk) * NX;
        #pragma unroll
        for (int r = 0; r < 8; r++) {
            const float* Er = Ea + (size_t)(2 * r) * NX;
            pa[r] = vA ? Er[m0 + mn] : 0.f;
            pb[r] = vB ? Er[n0 + mn] : 0.f;
        }
    };
    auto store_tiles = [&](int buf) {
        #pragma unroll
        for (int r = 0; r < 8; r++) {
            As[buf][kk + 2 * r][mn] = pa[r];
            Bs[buf][kk + 2 * r][mn] = pb[r];
        }
    };
    auto compute = [&](int buf) {
        #pragma unroll
        for (int k = 0; k < GK; k++) {
            float4 a0 = *reinterpret_cast<const float4*>(&As[buf][k][ty * 4]);
            float4 a1 = *reinterpret_cast<const float4*>(&As[buf][k][ty * 4 + 64]);
            ulonglong2 b01 = *reinterpret_cast<const ulonglong2*>(&Bs[buf][k][tx * 4]);
            ulonglong2 b23 = *reinterpret_cast<const ulonglong2*>(&Bs[buf][k][tx * 4 + 64]);
            float am[8] = {a0.x, a0.y, a0.z, a0.w, a1.x, a1.y, a1.z, a1.w};
            ull bp[4] = {b01.x, b01.y, b23.x, b23.y};
            #pragma unroll
            for (int ii = 0; ii < 8; ii++) {
                ull ap;
                PACK_DUP(ap, am[ii]);
                #pragma unroll
                for (int jp = 0; jp < 4; jp++)
                    FMA_X2(acc2[ii][jp], ap, bp[jp]);
            }
        }
    };

    load_tiles(0);
    store_tiles(0);
    __syncthreads();

    const int nk = CM / GK;   // 4
    for (int it = 0; it < nk; it++) {
        bool more = (it + 1) < nk;
        if (more) load_tiles((it + 1) * GK);
        compute(it & 1);
        if (more) { store_tiles((it + 1) & 1); __syncthreads(); }
    }

    float acc[8][8];
    #pragma unroll
    for (int ii = 0; ii < 8; ii++)
        #pragma unroll
        for (int jp = 0; jp < 4; jp++)
            UNPACK2(acc[ii][jp * 2], acc[ii][jp * 2 + 1], acc2[ii][jp]);

    #pragma unroll
    for (int ii = 0; ii < 8; ii++) {
        int m = m0 + ty * 4 + (ii & 3) + ((ii >> 2) << 6);
        if (m >= NX) continue;
        #pragma unroll
        for (int jp = 0; jp < 4; jp++)
            #pragma unroll
            for (int h = 0; h < 2; h++) {
                int n = n0 + tx * 4 + ((jp & 1) << 1) + h + ((jp >> 1) << 6);
                if (n < NX) Sb[(size_t)m * SPAD + n] = acc[ii][jp * 2 + h];
            }
    }
    if (i != j) {
        #pragma unroll
        for (int jp = 0; jp < 4; jp++)
            #pragma unroll
            for (int h = 0; h < 2; h++) {
                int n = n0 + tx * 4 + ((jp & 1) << 1) + h + ((jp >> 1) << 6);
                if (n >= NX) continue;
                float4 v0 = make_float4(acc[0][jp * 2 + h], acc[1][jp * 2 + h],
                                        acc[2][jp * 2 + h], acc[3][jp * 2 + h]);
                float4 v1 = make_float4(acc[4][jp * 2 + h], acc[5][jp * 2 + h],
                                        acc[6][jp * 2 + h], acc[7][jp * 2 + h]);
                *reinterpret_cast<float4*>(&Sb[(size_t)n * SPAD + m0 + ty * 4]) = v0;
                *reinterpret_cast<float4*>(&Sb[(size_t)n * SPAD + m0 + 64 + ty * 4]) = v1;
            }
    }
}

// ================= small GEMM: 32x64 tile, 128 threads =======
struct SmTask {
    const float* A; size_t sAb; int lda; int aT;
    const float* B; size_t sBb; int ldb;
    float* C; size_t sCb; int ldc;
    int M, N, K, Npad;
    const float* bias; int epi;
    const float* gamma; const float* beta; const float* mean; const float* var;
    const float* cb; size_t scb;
};

#define SBK 16
__global__ __launch_bounds__(128)
void gemm_sm_dual(SmTask t0, SmTask t1, int split)
{
    int by = blockIdx.y;
    bool second = (split > 0 && by >= split);
    const SmTask& t = second ? t1 : t0;
    int mt = second ? by - split : by;

    int b = blockIdx.z;
    const float* Ab = t.A + (size_t)b * t.sAb;
    const float* Bb = t.B + (size_t)b * t.sBb;
    float* Cb = t.C + (size_t)b * t.sCb;

    __shared__ float As[SBK][32];
    __shared__ float Bs[SBK][64];

    int tid = threadIdx.x;
    int tx = tid & 15, ty = tid >> 4;
    int m0 = mt * 32;

    ull acc2[4][2] = {};

    for (int k0 = 0; k0 < t.K; k0 += SBK) {
        if (!t.aT) {
            #pragma unroll
            for (int r = 0; r < 4; r++) {
                int idx = tid + r * 128;
                int tk = idx & 15, tm = idx >> 4;
                int gm = m0 + tm, gk = k0 + tk;
                As[tk][tm] = (gm < t.M && gk < t.K) ? Ab[(size_t)gm * t.lda + gk] : 0.f;
            }
        } else {
            #pragma unroll
            for (int r = 0; r < 4; r++) {
                int idx = tid + r * 128;
                int tm = idx & 31, tk = idx >> 5;
                int gm = m0 + tm, gk = k0 + tk;
                As[tk][tm] = (gm < t.M && gk < t.K) ? Ab[(size_t)gk * t.lda + gm] : 0.f;
            }
        }
        #pragma unroll
        for (int r = 0; r < 8; r++) {
            int idx = tid + r * 128;
            int tn = idx & 63, tk = idx >> 6;
            int gk = k0 + tk;
            Bs[tk][tn] = (tn < t.N && gk < t.K) ? Bb[(size_t)gk * t.ldb + tn] : 0.f;
        }
        __syncthreads();

        #pragma unroll
        for (int k = 0; k < SBK; k++) {
            float4 av = *reinterpret_cast<const float4*>(&As[k][ty * 4]);
            ulonglong2 bv = *reinterpret_cast<const ulonglong2*>(&Bs[k][tx * 4]);
            float a4[4] = {av.x, av.y, av.z, av.w};
            ull bp[2] = {bv.x, bv.y};
            #pragma unroll
            for (int i = 0; i < 4; i++) {
                ull ap;
                PACK_DUP(ap, a4[i]);
                #pragma unroll
                for (int jp = 0; jp < 2; jp++)
                    FMA_X2(acc2[i][jp], ap, bp[jp]);
            }
        }
        __syncthreads();
    }

    #pragma unroll
    for (int i = 0; i < 4; i++) {
        int m = m0 + ty * 4 + i;
        if (m >= t.M) continue;
        float bval = t.bias ? t.bias[m] : 0.f;
        float s = 1.f, sh = 0.f;
        if (t.epi == 1) {
            s = t.gamma[m] * rsqrtf(t.var[m] + EPSB);
            sh = t.beta[m] - t.mean[m] * s;
        }
        #pragma unroll
        for (int jp = 0; jp < 2; jp++) {
            float vlo, vhi;
            UNPACK2(vlo, vhi, acc2[i][jp]);
            float vv[2] = {vlo, vhi};
            #pragma unroll
            for (int h = 0; h < 2; h++) {
                int n = tx * 4 + jp * 2 + h;
                if (n >= t.Npad) continue;
                float v;
                if (n >= t.N) {
                    v = 0.f;
                } else {
                    v = vv[h] + bval;
                    if (t.epi == 1)      v = fmaxf(v * s + sh, 0.f);
                    else if (t.epi == 3) v += t.cb[(size_t)b * t.scb + n];
                }
                Cb[(size_t)m * t.ldc + n] = v;
            }
        }
    }
}

// ---------------- r[b][m] = bq . zf_t[b][:,m] ----------------
__global__ void rvec_kernel(const float* __restrict__ zf_t,
                            const float* __restrict__ bq,
                            float* __restrict__ r)
{
    int b = blockIdx.x;
    int m = threadIdx.x;
    if (m >= NZ) return;
    const float* z = zf_t + (size_t)b * CC * NZ;
    float acc = 0.f;
    for (int c = 0; c < CC; c++)
        acc += bq[c] * z[(size_t)c * NZ + m];
    r[b * NZ + m] = acc;
}

// ---- softmax over last dim (49); writes attn^T (rows 49..63 zeroed) ----
__global__ void softmax49_kernel(float* __restrict__ S, float* __restrict__ ST,
                                 int rows)
{
    int warp = (blockIdx.x * blockDim.x + threadIdx.x) >> 5;
    int lane = threadIdx.x & 31;
    if (warp >= rows) return;
    float* row = S + (size_t)warp * NZ;
    int b = warp / NX;
    int n = warp - b * NX;
    float v0 = row[lane];
    float v1 = (lane + 32 < NZ) ? row[lane + 32] : -INFINITY;
    float mx = fmaxf(v0, v1);
    #pragma unroll
    for (int o = 16; o; o >>= 1) mx = fmaxf(mx, __shfl_xor_sync(0xFFFFFFFFu, mx, o));
    float e0 = expf(v0 - mx);
    float e1 = (lane + 32 < NZ) ? expf(v1 - mx) : 0.f;
    float sm = e0 + e1;
    #pragma unroll
    for (int o = 16; o; o >>= 1) sm += __shfl_xor_sync(0xFFFFFFFFu, sm, o);
    float inv = 1.f / sm;
    float* STb = ST + (size_t)b * UPAD * NX;
    STb[(size_t)lane * NX + n] = e0 * inv;
    STb[(size_t)(lane + 32) * NX + n] = (lane + 32 < NZ) ? e1 * inv : 0.f;
}

// ---------------- conv3x3 + BN + PReLU (FFMA2, OCB=8) --------
#define CI 8
#define OCB 8
#define PW 33

__global__ __launch_bounds__(256, 2)
void conv3_kernel(const float* __restrict__ gat, const float* __restrict__ Wm,
                  const float* __restrict__ bm,
                  const float* __restrict__ mg, const float* __restrict__ mb,
                  const float* __restrict__ mm, const float* __restrict__ mv,
                  const float* __restrict__ pa,
                  float* __restrict__ e)
{
    int b = blockIdx.x;
    int ocg = blockIdx.y;
    __shared__ float in_s[CI][PW * PW];
    __shared__ ull   w2_s[OCB][CI][9];
    int tid = threadIdx.x;

    for (int idx = tid; idx < CI * PW * PW; idx += 256)
        (&in_s[0][0])[idx] = 0.f;
    __syncthreads();

    int y  = tid >> 3;
    int x0 = (tid & 7) << 2;
    bool active = (tid < 248);

    ull acc2[OCB][2] = {};
    const float* gb = gat + (size_t)b * CC * NX;

    for (int c0 = 0; c0 < CC; c0 += CI) {
        for (int idx = tid; idx < CI * NX; idx += 256) {
            int c = idx / NX, p = idx - c * NX;
            int yy = p / 31, xx = p - yy * 31;
            in_s[c][(yy + 1) * PW + (xx + 1)] = gb[(size_t)(c0 + c) * NX + p];
        }
        for (int idx = tid; idx < OCB * CI * 9; idx += 256) {
            int o = idx / (CI * 9), rem = idx % (CI * 9);
            int c = rem / 9, k = rem % 9;
            float w = Wm[((size_t)(ocg * OCB + o) * CC + (c0 + c)) * 9 + k];
            ull wp; PACK_DUP(wp, w);
            w2_s[o][c][k] = wp;
        }
        __syncthreads();

        if (active) {
            #pragma unroll
            for (int c = 0; c < CI; c++) {
                float nb[3][6];
                #pragma unroll
                for (int dy = 0; dy < 3; dy++)
                    #pragma unroll
                    for (int dx = 0; dx < 6; dx++)
                        nb[dy][dx] = (x0 + dx <= PW - 1)
                                   ? in_s[c][(y + dy) * PW + (x0 + dx)] : 0.f;
                ull nb2[3][3][2];
                #pragma unroll
                for (int dy = 0; dy < 3; dy++)
                    #pragma unroll
                    for (int dx = 0; dx < 3; dx++) {
                        PACK2(nb2[dy][dx][0], nb[dy][dx + 0], nb[dy][dx + 1]);
                        PACK2(nb2[dy][dx][1], nb[dy][dx + 2], nb[dy][dx + 3]);
                    }
                #pragma unroll
                for (int o = 0; o < OCB; o++) {
                    #pragma unroll
                    for (int dy = 0; dy < 3; dy++)
                        #pragma unroll
                        for (int dx = 0; dx < 3; dx++) {
                            ull wp = w2_s[o][c][dy * 3 + dx];
                            FMA_X2(acc2[o][0], nb2[dy][dx][0], wp);
                            FMA_X2(acc2[o][1], nb2[dy][dx][1], wp);
                        }
                }
            }
        }
        __syncthreads();
    }

    if (active) {
        float a = pa[0];
        #pragma unroll
        for (int o = 0; o < OCB; o++) {
            int oc = ocg * OCB + o;
            float s = mg[oc] * rsqrtf(mv[oc] + EPSB);
            float sh = mb[oc] - mm[oc] * s;
            float av[4];
            UNPACK2(av[0], av[1], acc2[o][0]);
            UNPACK2(av[2], av[3], acc2[o][1]);
            #pragma unroll
            for (int p = 0; p < 4; p++) {
                int x = x0 + p;
                if (x < 31) {
                    float v = (av[p] + bm[oc]) * s + sh;
                    v = (v >= 0.f) ? v : a * v;
                    e[(size_t)b * CM * NX + (size_t)oc * NX + (y * 31 + x)] = v;
                }
            }
        }
    }
}

// ---- tiled transpose gat->gatT; blocks (z==0,y==0) also zero colcnt ----
__global__ void transpose_kernel(const float* __restrict__ in, float* __restrict__ outT,
                                 int* __restrict__ cnt)
{
    __shared__ float tile[32][33];
    int b = blockIdx.z;
    int n0 = blockIdx.x * 32;
    int c0 = blockIdx.y * 32;
    int lx = threadIdx.x, ly = threadIdx.y;
    if (blockIdx.z == 0 && blockIdx.y == 0) {
        int base = blockIdx.x * 256 + ly * 32 + lx;
        for (int i = base; i < BATCH * NX; i += 31 * 256) cnt[i] = 0;
    }
    #pragma unroll
    for (int r = 0; r < 4; r++) {
        int c = c0 + ly + r * 8, n = n0 + lx;
        if (n < NX) tile[ly + r * 8][lx] = in[((size_t)b * CC + c) * NX + n];
    }
    __syncthreads();
    #pragma unroll
    for (int r = 0; r < 4; r++) {
        int n = n0 + ly + r * 8, c = c0 + lx;
        if (n < NX) outT[((size_t)b * NX + n) * CC + c] = tile[lx][ly + r * 8];
    }
}

// ---------------- sparsemax + scatter nonzeros to packed column lists ------
__global__ void sparsemax_scatter_kernel(const float* __restrict__ S,
                                         float2* __restrict__ colpk,
                                         int*    __restrict__ colcnt,
                                         int rows)
{
    int warp = (blockIdx.x * blockDim.x + threadIdx.x) >> 5;
    int lane = threadIdx.x & 31;
    if (warp >= rows) return;
    const float* row = S + (size_t)warp * SPAD;
    int b = warp / NX;
    int n = warp - b * NX;

    float v[31];
    #pragma unroll
    for (int t = 0; t < 31; t++) {
        int idx = lane + 32 * t;
        v[t] = (idx < NX) ? row[idx] : -INFINITY;
    }
    float mx = -INFINITY;
    #pragma unroll
    for (int t = 0; t < 31; t++) mx = fmaxf(mx, v[t]);
    #pragma unroll
    for (int o = 16; o; o >>= 1) mx = fmaxf(mx, __shfl_xor_sync(0xFFFFFFFFu, mx, o));
    #pragma unroll
    for (int t = 0; t < 31; t++) v[t] -= mx;

    float lo = -1.f, hi = 0.f;
    for (int it = 0; it < 26; it++) {
        float mid = 0.5f * (lo + hi);
        float f = 0.f;
        #pragma unroll
        for (int t = 0; t < 31; t++) f += fmaxf(v[t] - mid, 0.f);
        #pragma unroll
        for (int o = 16; o; o >>= 1) f += __shfl_xor_sync(0xFFFFFFFFu, f, o);
        if (f >= 1.f) lo = mid; else hi = mid;
    }
    float tm = 0.5f * (lo + hi);
    float cnt = 0.f, sm = 0.f;
    #pragma unroll
    for (int t = 0; t < 31; t++) {
        if (v[t] > tm) { cnt += 1.f; sm += v[t]; }
    }
    #pragma unroll
    for (int o = 16; o; o >>= 1) {
        cnt += __shfl_xor_sync(0xFFFFFFFFu, cnt, o);
        sm  += __shfl_xor_sync(0xFFFFFFFFu, sm,  o);
    }
    float tau = (sm - 1.f) / cnt;

    #pragma unroll
    for (int t = 0; t < 31; t++) {
        int idx = lane + 32 * t;
        if (idx < NX) {
            float p = v[t] - tau;
            if (p > 0.f) {
                int col = b * NX + idx;
                int slot = atomicAdd(&colcnt[col], 1);
                colpk[(size_t)col * NX + slot] = make_float2(p, __int_as_float(n));
            }
        }
    }
}

// ---- sparse out: out[b,:,m] = gat[b,:,m] + sum_n p * gat[b,:,n] ----
#define MCOLS 32
__global__ __launch_bounds__(256, 4)
void sparse_out_kernel(const float* __restrict__ gatT,
                       const float2* __restrict__ colpk,
                       const int*    __restrict__ colcnt,
                       float* __restrict__ out)
{
    int b  = blockIdx.y;
    int m0 = blockIdx.x * MCOLS;
    int tid = threadIdx.x;
    __shared__ float accs[MCOLS][257];

    const float* gT = gatT + (size_t)b * NX * CC;

    for (int mi = 0; mi < MCOLS; mi++) {
        int m = m0 + mi;
        if (m >= NX) break;
        float acc = gT[(size_t)m * CC + tid];
        int cnt = colcnt[b * NX + m];
        const float2* pk = colpk + (size_t)(b * NX + m) * NX;
        int s = 0;
        for (; s + 4 <= cnt; s += 4) {
            float2 q0 = pk[s], q1 = pk[s + 1], q2 = pk[s + 2], q3 = pk[s + 3];
            float v0 = gT[(size_t)__float_as_int(q0.y) * CC + tid];
            float v1 = gT[(size_t)__float_as_int(q1.y) * CC + tid];
            float v2 = gT[(size_t)__float_as_int(q2.y) * CC + tid];
            float v3 = gT[(size_t)__float_as_int(q3.y) * CC + tid];
            acc += q0.x * v0;
            acc += q1.x * v1;
            acc += q2.x * v2;
            acc += q3.x * v3;
        }
        for (; s < cnt; s++) {
            float2 q = pk[s];
            acc += q.x * gT[(size_t)__float_as_int(q.y) * CC + tid];
        }
        accs[mi][tid] = acc;
    }
    __syncthreads();

    #pragma unroll
    for (int r = 0; r < MCOLS; r++) {
        int idx = tid + r * 256;
        int c = idx >> 5, mi = idx & 31;
        int m = m0 + mi;
        if (m < NX)
            out[((size_t)b * CC + c) * NX + m] = accs[mi][c];
    }
}

// ---------------- launch ----------------
extern "C" void kernel_launch(void* const* d_in, const int* in_sizes, int n_in,
                              void* d_out, int out_size)
{
    const float* zf  = (const float*)d_in[0];
    const float* xf  = (const float*)d_in[1];
    const float* Wq  = (const float*)d_in[2];
    const float* bq  = (const float*)d_in[3];
    const float* Ws  = (const float*)d_in[4];
    const float* bs  = (const float*)d_in[5];
    const float* Wg  = (const float*)d_in[6];
    const float* bg  = (const float*)d_in[7];
    const float* g_gamma = (const float*)d_in[8];
    const float* g_beta  = (const float*)d_in[9];
    const float* g_mean  = (const float*)d_in[10];
    const float* g_var   = (const float*)d_in[11];
    const float* Wfi = (const float*)d_in[12];
    const float* bfi = (const float*)d_in[13];
    const float* fi_gamma = (const float*)d_in[14];
    const float* fi_beta  = (const float*)d_in[15];
    const float* fi_mean  = (const float*)d_in[16];
    const float* fi_var   = (const float*)d_in[17];
    const float* Wm  = (const float*)d_in[18];
    const float* bm  = (const float*)d_in[19];
    const float* m_gamma = (const float*)d_in[20];
    const float* m_beta  = (const float*)d_in[21];
    const float* m_mean  = (const float*)d_in[22];
    const float* m_var   = (const float*)d_in[23];
    const float* prelu_a = (const float*)d_in[24];
    float* out = (float*)d_out;

    float *xf_g, *zf_t, *zf_g, *tp, *u, *r, *sim, *simT, *gat, *gatT, *e, *S;
    float2 *colpk; int *colcnt;
    cudaGetSymbolAddress((void**)&xf_g, g_xf_g);
    cudaGetSymbolAddress((void**)&zf_t, g_zf_t);
    cudaGetSymbolAddress((void**)&zf_g, g_zf_g);
    cudaGetSymbolAddress((void**)&tp,   g_tp);
    cudaGetSymbolAddress((void**)&u,    g_u);
    cudaGetSymbolAddress((void**)&r,    g_r);
    cudaGetSymbolAddress((void**)&sim,  g_sim);
    cudaGetSymbolAddress((void**)&simT, g_simT);
    cudaGetSymbolAddress((void**)&gat,  g_gat);
    cudaGetSymbolAddress((void**)&gatT, g_gatT);
    cudaGetSymbolAddress((void**)&e,    g_e);
    cudaGetSymbolAddress((void**)&S,    g_S);
    cudaGetSymbolAddress((void**)&colpk, g_colpk);
    cudaGetSymbolAddress((void**)&colcnt, g_colcnt);

    dim3 blk(256);
    const size_t sX  = (size_t)CC * NX;
    const size_t sZ  = (size_t)CC * NZ;
    const size_t sU  = (size_t)CC * UPAD;
    const size_t sSim = (size_t)NX * NZ;
    const size_t sST = (size_t)UPAD * NX;

    SmTask tA = { Ws, 0, CC, 0,  zf, sZ, NZ,  zf_t, sZ, NZ,  CC, NZ, CC, NZ,
                  bs, 0,  nullptr, nullptr, nullptr, nullptr,  nullptr, 0 };
    SmTask tB = { Wg, 0, CC, 0,  zf, sZ, NZ,  zf_g, sZ, NZ,  CC, NZ, CC, NZ,
                  bg, 1,  g_gamma, g_beta, g_mean, g_var,  nullptr, 0 };
    SmTask tD = { Wq, 0, CC, 1,  zf_t, sZ, NZ,  tp, sZ, NZ,  CC, NZ, CC, NZ,
                  nullptr, 0,  nullptr, nullptr, nullptr, nullptr,  nullptr, 0 };
    SmTask tE = { Wfi, 0, 2 * CC, 0,  zf_g, sZ, NZ,  u, sU, UPAD,  CC, NZ, CC, UPAD,
                  nullptr, 0,  nullptr, nullptr, nullptr, nullptr,  nullptr, 0 };
    SmTask tG = { xf, sX, NX, 1,  tp, sZ, NZ,  sim, sSim, NZ,  NX, NZ, CC, NZ,
                  nullptr, 3,  nullptr, nullptr, nullptr, nullptr,  r, NZ };

    // A+B) zf_t and zf_g
    gemm_sm_dual<<<dim3(1, 16, BATCH), 128>>>(tA, tB, 8);
    // C) r
    rvec_kernel<<<BATCH, 64>>>(zf_t, bq, r);
    // D+E) t' and u (u zero-padded to 64 cols)
    gemm_sm_dual<<<dim3(1, 16, BATCH), 128>>>(tD, tE, 8);
    // F) xf_g = relu(bn(Wg * xf + bg))
    gemm128f_kernel<<<dim3(8, 2, BATCH), blk>>>(
        Wg, 0, CC,  nullptr, 0, 0,
        xf, sX, NX,  nullptr, 0, 0,  -1,
        xf_g, sX, NX,  CC, NX, CC,  bg, 1,
        g_gamma, g_beta, g_mean, g_var);
    // G) sim = xf^T t' + r
    gemm_sm_dual<<<dim3(1, 31, BATCH), 128>>>(tG, tG, 0);
    // H) softmax -> attn^T (rows 49..63 zeroed)
    softmax49_kernel<<<(BATCH * NX + 7) / 8, blk>>>(sim, simT, BATCH * NX);
    // I) gat = relu(bn([u|Wfi_R]*[attn^T; xf_g] + bfi)), K=320, ksplit=64
    gemm128f_kernel<<<dim3(8, 2, BATCH), blk>>>(
        u, sU, UPAD,  Wfi + CC, 0, 2 * CC,
        simT, sST, NX,  xf_g, sX, NX,  UPAD,
        gat, sX, NX,  CC, NX, UPAD + CC,  bfi, 1,
        fi_gamma, fi_beta, fi_mean, fi_var);
    // J) gatT = transpose(gat); zero colcnt
    transpose_kernel<<<dim3(31, 8, BATCH), dim3(32, 8)>>>(gat, gatT, colcnt);
    // K) e = prelu(bn(conv3x3(gat) + bm))
    conv3_kernel<<<dim3(BATCH, CM / OCB), blk>>>(
        gat, Wm, bm, m_gamma, m_beta, m_mean, m_var, prelu_a, e);
    // L) S = e^T e, symmetric (36 upper-triangle tile pairs + mirror)
    gemm_symL_kernel<<<dim3(36, 1, BATCH), blk>>>(e, S);
    // M) sparsemax rows of S -> packed sparse column lists
    sparsemax_scatter_kernel<<<(BATCH * NX + 7) / 8, blk>>>(
        S, colpk, colcnt, BATCH * NX);
    // N) out = gat + gat * P (sparse)
    sparse_out_kernel<<<dim3((NX + MCOLS - 1) / MCOLS, BATCH), blk>>>(
        gatT, colpk, colcnt, out);
}

// round 15
// speedup vs baseline: 1.0741x; 1.0230x over previous
#include <cuda_runtime.h>
#include <math.h>

#define BATCH 32
#define CC 256
#define CM 64
#define NX 961
#define NZ 49
#define EPSB 1e-5f
#define SPAD 976     // padded leading dim of S (16-float aligned)
#define UPAD 64      // padded K-prefix (u cols / attn^T rows)

typedef unsigned long long ull;

#define FMA_X2(d, a, b) \
    asm("fma.rn.f32x2 %0, %1, %2, %0;" : "+l"(d) : "l"(a), "l"(b))
#define PACK_DUP(d, f) \
    asm("mov.b64 %0, {%1, %1};" : "=l"(d) : "f"(f))
#define PACK2(d, flo, fhi) \
    asm("mov.b64 %0, {%1, %2};" : "=l"(d) : "f"(flo), "f"(fhi))
#define UNPACK2(flo, fhi, s) \
    asm("mov.b64 {%0, %1}, %2;" : "=f"(flo), "=f"(fhi) : "l"(s))

// ---------------- scratch (device globals; no allocation) ----------------
__device__ float g_xf_g[BATCH * CC * NX];
__device__ float g_zf_t[BATCH * CC * NZ];
__device__ float g_zf_g[BATCH * CC * NZ];
__device__ float g_tp  [BATCH * CC * NZ];    // t' = Wq^T zf_t
__device__ float g_u   [BATCH * CC * UPAD];  // u = Wfi_left zf_g (cols 49..63 = 0)
__device__ float g_r   [BATCH * NZ];
__device__ float g_sim [BATCH * NX * NZ];
__device__ float g_simT[BATCH * UPAD * NX];  // attn^T, rows 49..63 = 0
__device__ float g_gat [BATCH * CC * NX];
__device__ float g_gatT[BATCH * NX * CC];
__device__ float g_e   [BATCH * CM * NX];
__device__ float g_S   [(size_t)BATCH * NX * SPAD];
__device__ float2 g_colpk[(size_t)BATCH * NX * NX];
__device__ int   g_colcnt[BATCH * NX];

// ============ 128x128 fp32 GEMM: R12 layout + double-buffered smem ====
// Requires K % 16 == 0 and (ksplit < 0 or ksplit % 16 == 0).
#define GM 128
#define GN 128
#define GK 16
#define GPAD 132

__global__ __launch_bounds__(256, 2)
void gemm128f_kernel(
    const float* __restrict__ A, size_t sAb, int lda,
    const float* __restrict__ A2, size_t sA2b, int lda2,
    const float* __restrict__ B, size_t sBb, int ldb,
    const float* __restrict__ B2, size_t sB2b, int ldb2,
    int ksplit,
    float* __restrict__ Cout, size_t sCb, int ldc,
    int M, int N, int K,
    const float* __restrict__ bias, int epi,
    const float* __restrict__ gamma, const float* __restrict__ beta,
    const float* __restrict__ mean,  const float* __restrict__ var)
{
    __shared__ float As[2][GK][GPAD];
    __shared__ float Bs[2][GK][GPAD];

    int b = blockIdx.z;
    const float* Ab  = A + (size_t)b * sAb;
    const float* A2b = A2 ? (A2 + (size_t)b * sA2b) : nullptr;
    const float* Bb  = B + (size_t)b * sBb;
    const float* B2b = B2 ? (B2 + (size_t)b * sB2b) : nullptr;
    float* Cb = Cout + (size_t)b * sCb;

    int m0 = blockIdx.y * GM;
    int n0 = blockIdx.x * GN;
    int tid = threadIdx.x;
    int tx = tid & 15, ty = tid >> 4;

    // hoisted mappings (k0-invariant)
    int kA = tid & 15;
    int lmA[8]; bool vA[8];
    #pragma unroll
    for (int r = 0; r < 8; r++) {
        lmA[r] = (tid >> 4) + r * 16;
        vA[r] = (m0 + lmA[r]) < M;
    }
    int nB = tid & 127;
    bool vB = (n0 + nB) < N;
    int kB0 = tid >> 7;

    ull acc2[8][4] = {};
    float pa[8], pb[8];

    auto load_tiles = [&](int k0) {
        const float* Asrc; int ald;
        const float* Bsrc; int bld;
        if (ksplit >= 0 && k0 >= ksplit) {
            Asrc = A2b + (k0 - ksplit); ald = lda2;
            Bsrc = B2b + (size_t)(k0 - ksplit) * ldb2; bld = ldb2;
        } else {
            Asrc = Ab + k0; ald = lda;
            Bsrc = Bb + (size_t)k0 * ldb; bld = ldb;
        }
        #pragma unroll
        for (int r = 0; r < 8; r++)
            pa[r] = vA[r] ? Asrc[(size_t)(m0 + lmA[r]) * ald + kA] : 0.f;
        const float* Bp = Bsrc + (size_t)kB0 * bld + (n0 + nB);
        #pragma unroll
        for (int r = 0; r < 8; r++)
            pb[r] = vB ? Bp[(size_t)(2 * r) * bld] : 0.f;
    };
    auto store_tiles = [&](int buf) {
        #pragma unroll
        for (int r = 0; r < 8; r++) As[buf][kA][lmA[r]] = pa[r];
        #pragma unroll
        for (int r = 0; r < 8; r++) Bs[buf][kB0 + 2 * r][nB] = pb[r];
    };
    auto compute = [&](int buf) {
        #pragma unroll
        for (int k = 0; k < GK; k++) {
            float4 a0 = *reinterpret_cast<const float4*>(&As[buf][k][ty * 4]);
            float4 a1 = *reinterpret_cast<const float4*>(&As[buf][k][ty * 4 + 64]);
            ulonglong2 b01 = *reinterpret_cast<const ulonglong2*>(&Bs[buf][k][tx * 4]);
            ulonglong2 b23 = *reinterpret_cast<const ulonglong2*>(&Bs[buf][k][tx * 4 + 64]);
            float am[8] = {a0.x, a0.y, a0.z, a0.w, a1.x, a1.y, a1.z, a1.w};
            ull bp[4] = {b01.x, b01.y, b23.x, b23.y};
            #pragma unroll
            for (int i = 0; i < 8; i++) {
                ull ap;
                PACK_DUP(ap, am[i]);
                #pragma unroll
                for (int jp = 0; jp < 4; jp++)
                    FMA_X2(acc2[i][jp], ap, bp[jp]);
            }
        }
    };

    load_tiles(0);
    store_tiles(0);
    __syncthreads();

    int nk = K / GK;
    for (int it = 0; it < nk; it++) {
        bool more = (it + 1) < nk;
        if (more) load_tiles((it + 1) * GK);
        compute(it & 1);
        if (more) { store_tiles((it + 1) & 1); __syncthreads(); }
    }

    #pragma unroll
    for (int i = 0; i < 8; i++) {
        int m = m0 + ty * 4 + (i & 3) + ((i >> 2) << 6);
        if (m >= M) continue;
        float bval = bias ? bias[m] : 0.f;
        float s = 1.f, sh = 0.f;
        if (epi == 1) {
            s = gamma[m] * rsqrtf(var[m] + EPSB);
            sh = beta[m] - mean[m] * s;
        }
        #pragma unroll
        for (int jp = 0; jp < 4; jp++) {
            float vlo, vhi;
            UNPACK2(vlo, vhi, acc2[i][jp]);
            float vv[2] = {vlo, vhi};
            #pragma unroll
            for (int h = 0; h < 2; h++) {
                int n = n0 + tx * 4 + ((jp & 1) << 1) + h + ((jp >> 1) << 6);
                if (n >= N) continue;
                float v = vv[h] + bval;
                if (epi == 1) v = fmaxf(v * s + sh, 0.f);
                Cb[(size_t)m * ldc + n] = v;
            }
        }
    }
}

// ============ symmetric S = e^T e: double-buffered, mirror ============
__global__ __launch_bounds__(256, 2)
void gemm_symL_kernel(const float* __restrict__ e, float* __restrict__ S)
{
    __shared__ float As[2][GK][GPAD];
    __shared__ float Bs[2][GK][GPAD];

    int b = blockIdx.z;
    const float* E = e + (size_t)b * CM * NX;
    float* Sb = S + (size_t)b * NX * SPAD;

    int lin = blockIdx.x, i = 0;
    while (lin >= 8 - i) { lin -= 8 - i; i++; }
    int j = i + lin;
    int m0 = i * 128, n0 = j * 128;

    int tid = threadIdx.x, tx = tid & 15, ty = tid >> 4;
    int mn = tid & 127;
    int kk = tid >> 7;
    bool vA = (m0 + mn) < NX;
    bool vB = (n0 + mn) < NX;

    ull acc2[8][4] = {};
    float pa[8], pb[8];

    auto load_tiles = [&](int k0) {
        const float* Ea = E + (size_t)(k0 + kk) * NX;
        #pragma unroll
        for (int r = 0; r < 8; r++) {
            const float* Er = Ea + (size_t)(2 * r) * NX;
            pa[r] = vA ? Er[m0 + mn] : 0.f;
            pb[r] = vB ? Er[n0 + mn] : 0.f;
        }
    };
    auto store_tiles = [&](int buf) {
        #pragma unroll
        for (int r = 0; r < 8; r++) {
            As[buf][kk + 2 * r][mn] = pa[r];
            Bs[buf][kk + 2 * r][mn] = pb[r];
        }
    };
    auto compute = [&](int buf) {
        #pragma unroll
        for (int k = 0; k < GK; k++) {
            float4 a0 = *reinterpret_cast<const float4*>(&As[buf][k][ty * 4]);
            float4 a1 = *reinterpret_cast<const float4*>(&As[buf][k][ty * 4 + 64]);
            ulonglong2 b01 = *reinterpret_cast<const ulonglong2*>(&Bs[buf][k][tx * 4]);
            ulonglong2 b23 = *reinterpret_cast<const ulonglong2*>(&Bs[buf][k][tx * 4 + 64]);
            float am[8] = {a0.x, a0.y, a0.z, a0.w, a1.x, a1.y, a1.z, a1.w};
            ull bp[4] = {b01.x, b01.y, b23.x, b23.y};
            #pragma unroll
            for (int ii = 0; ii < 8; ii++) {
                ull ap;
                PACK_DUP(ap, am[ii]);
                #pragma unroll
                for (int jp = 0; jp < 4; jp++)
                    FMA_X2(acc2[ii][jp], ap, bp[jp]);
            }
        }
    };

    load_tiles(0);
    store_tiles(0);
    __syncthreads();

    const int nk = CM / GK;   // 4
    for (int it = 0; it < nk; it++) {
        bool more = (it + 1) < nk;
        if (more) load_tiles((it + 1) * GK);
        compute(it & 1);
        if (more) { store_tiles((it + 1) & 1); __syncthreads(); }
    }

    float acc[8][8];
    #pragma unroll
    for (int ii = 0; ii < 8; ii++)
        #pragma unroll
        for (int jp = 0; jp < 4; jp++)
            UNPACK2(acc[ii][jp * 2], acc[ii][jp * 2 + 1], acc2[ii][jp]);

    #pragma unroll
    for (int ii = 0; ii < 8; ii++) {
        int m = m0 + ty * 4 + (ii & 3) + ((ii >> 2) << 6);
        if (m >= NX) continue;
        #pragma unroll
        for (int jp = 0; jp < 4; jp++)
            #pragma unroll
            for (int h = 0; h < 2; h++) {
                int n = n0 + tx * 4 + ((jp & 1) << 1) + h + ((jp >> 1) << 6);
                if (n < NX) Sb[(size_t)m * SPAD + n] = acc[ii][jp * 2 + h];
            }
    }
    if (i != j) {
        #pragma unroll
        for (int jp = 0; jp < 4; jp++)
            #pragma unroll
            for (int h = 0; h < 2; h++) {
                int n = n0 + tx * 4 + ((jp & 1) << 1) + h + ((jp >> 1) << 6);
                if (n >= NX) continue;
                float4 v0 = make_float4(acc[0][jp * 2 + h], acc[1][jp * 2 + h],
                                        acc[2][jp * 2 + h], acc[3][jp * 2 + h]);
                float4 v1 = make_float4(acc[4][jp * 2 + h], acc[5][jp * 2 + h],
                                        acc[6][jp * 2 + h], acc[7][jp * 2 + h]);
                *reinterpret_cast<float4*>(&Sb[(size_t)n * SPAD + m0 + ty * 4]) = v0;
                *reinterpret_cast<float4*>(&Sb[(size_t)n * SPAD + m0 + 64 + ty * 4]) = v1;
            }
    }
}

// ================= small GEMM: 32x64 tile, 128 threads =======
struct SmTask {
    const float* A; size_t sAb; int lda; int aT;
    const float* B; size_t sBb; int ldb;
    float* C; size_t sCb; int ldc;
    int M, N, K, Npad;
    const float* bias; int epi;
    const float* gamma; const float* beta; const float* mean; const float* var;
    const float* cb; size_t scb;
};

#define SBK 16
__global__ __launch_bounds__(128)
void gemm_sm_dual(SmTask t0, SmTask t1, int split)
{
    int by = blockIdx.y;
    bool second = (split > 0 && by >= split);
    const SmTask& t = second ? t1 : t0;
    int mt = second ? by - split : by;

    int b = blockIdx.z;
    const float* Ab = t.A + (size_t)b * t.sAb;
    const float* Bb = t.B + (size_t)b * t.sBb;
    float* Cb = t.C + (size_t)b * t.sCb;

    __shared__ float As[SBK][32];
    __shared__ float Bs[SBK][64];

    int tid = threadIdx.x;
    int tx = tid & 15, ty = tid >> 4;
    int m0 = mt * 32;

    ull acc2[4][2] = {};

    for (int k0 = 0; k0 < t.K; k0 += SBK) {
        if (!t.aT) {
            #pragma unroll
            for (int r = 0; r < 4; r++) {
                int idx = tid + r * 128;
                int tk = idx & 15, tm = idx >> 4;
                int gm = m0 + tm, gk = k0 + tk;
                As[tk][tm] = (gm < t.M && gk < t.K) ? Ab[(size_t)gm * t.lda + gk] : 0.f;
            }
        } else {
            #pragma unroll
            for (int r = 0; r < 4; r++) {
                int idx = tid + r * 128;
                int tm = idx & 31, tk = idx >> 5;
                int gm = m0 + tm, gk = k0 + tk;
                As[tk][tm] = (gm < t.M && gk < t.K) ? Ab[(size_t)gk * t.lda + gm] : 0.f;
            }
        }
        #pragma unroll
        for (int r = 0; r < 8; r++) {
            int idx = tid + r * 128;
            int tn = idx & 63, tk = idx >> 6;
            int gk = k0 + tk;
            Bs[tk][tn] = (tn < t.N && gk < t.K) ? Bb[(size_t)gk * t.ldb + tn] : 0.f;
        }
        __syncthreads();

        #pragma unroll
        for (int k = 0; k < SBK; k++) {
            float4 av = *reinterpret_cast<const float4*>(&As[k][ty * 4]);
            ulonglong2 bv = *reinterpret_cast<const ulonglong2*>(&Bs[k][tx * 4]);
            float a4[4] = {av.x, av.y, av.z, av.w};
            ull bp[2] = {bv.x, bv.y};
            #pragma unroll
            for (int i = 0; i < 4; i++) {
                ull ap;
                PACK_DUP(ap, a4[i]);
                #pragma unroll
                for (int jp = 0; jp < 2; jp++)
                    FMA_X2(acc2[i][jp], ap, bp[jp]);
            }
        }
        __syncthreads();
    }

    #pragma unroll
    for (int i = 0; i < 4; i++) {
        int m = m0 + ty * 4 + i;
        if (m >= t.M) continue;
        float bval = t.bias ? t.bias[m] : 0.f;
        float s = 1.f, sh = 0.f;
        if (t.epi == 1) {
            s = t.gamma[m] * rsqrtf(t.var[m] + EPSB);
            sh = t.beta[m] - t.mean[m] * s;
        }
        #pragma unroll
        for (int jp = 0; jp < 2; jp++) {
            float vlo, vhi;
            UNPACK2(vlo, vhi, acc2[i][jp]);
            float vv[2] = {vlo, vhi};
            #pragma unroll
            for (int h = 0; h < 2; h++) {
                int n = tx * 4 + jp * 2 + h;
                if (n >= t.Npad) continue;
                float v;
                if (n >= t.N) {
                    v = 0.f;
                } else {
                    v = vv[h] + bval;
                    if (t.epi == 1)      v = fmaxf(v * s + sh, 0.f);
                    else if (t.epi == 3) v += t.cb[(size_t)b * t.scb + n];
                }
                Cb[(size_t)m * t.ldc + n] = v;
            }
        }
    }
}

// ---------------- r[b][m] = bq . zf_t[b][:,m] ----------------
__global__ void rvec_kernel(const float* __restrict__ zf_t,
                            const float* __restrict__ bq,
                            float* __restrict__ r)
{
    int b = blockIdx.x;
    int m = threadIdx.x;
    if (m >= NZ) return;
    const float* z = zf_t + (size_t)b * CC * NZ;
    float acc = 0.f;
    for (int c = 0; c < CC; c++)
        acc += bq[c] * z[(size_t)c * NZ + m];
    r[b * NZ + m] = acc;
}

// ---- softmax over last dim (49); writes attn^T (rows 49..63 zeroed) ----
__global__ void softmax49_kernel(float* __restrict__ S, float* __restrict__ ST,
                                 int rows)
{
    int warp = (blockIdx.x * blockDim.x + threadIdx.x) >> 5;
    int lane = threadIdx.x & 31;
    if (warp >= rows) return;
    float* row = S + (size_t)warp * NZ;
    int b = warp / NX;
    int n = warp - b * NX;
    float v0 = row[lane];
    float v1 = (lane + 32 < NZ) ? row[lane + 32] : -INFINITY;
    float mx = fmaxf(v0, v1);
    #pragma unroll
    for (int o = 16; o; o >>= 1) mx = fmaxf(mx, __shfl_xor_sync(0xFFFFFFFFu, mx, o));
    float e0 = expf(v0 - mx);
    float e1 = (lane + 32 < NZ) ? expf(v1 - mx) : 0.f;
    float sm = e0 + e1;
    #pragma unroll
    for (int o = 16; o; o >>= 1) sm += __shfl_xor_sync(0xFFFFFFFFu, sm, o);
    float inv = 1.f / sm;
    float* STb = ST + (size_t)b * UPAD * NX;
    STb[(size_t)lane * NX + n] = e0 * inv;
    STb[(size_t)(lane + 32) * NX + n] = (lane + 32 < NZ) ? e1 * inv : 0.f;
}

// ---------------- conv3x3 + BN + PReLU (FFMA2, OCB=8) --------
#define CI 8
#define OCB 8
#define PW 33

__global__ __launch_bounds__(256, 2)
void conv3_kernel(const float* __restrict__ gat, const float* __restrict__ Wm,
                  const float* __restrict__ bm,
                  const float* __restrict__ mg, const float* __restrict__ mb,
                  const float* __restrict__ mm, const float* __restrict__ mv,
                  const float* __restrict__ pa,
                  float* __restrict__ e)
{
    int b = blockIdx.x;
    int ocg = blockIdx.y;
    __shared__ float in_s[CI][PW * PW];
    __shared__ ull   w2_s[OCB][CI][9];
    int tid = threadIdx.x;

    for (int idx = tid; idx < CI * PW * PW; idx += 256)
        (&in_s[0][0])[idx] = 0.f;
    __syncthreads();

    int y  = tid >> 3;
    int x0 = (tid & 7) << 2;
    bool active = (tid < 248);

    ull acc2[OCB][2] = {};
    const float* gb = gat + (size_t)b * CC * NX;

    for (int c0 = 0; c0 < CC; c0 += CI) {
        for (int idx = tid; idx < CI * NX; idx += 256) {
            int c = idx / NX, p = idx - c * NX;
            int yy = p / 31, xx = p - yy * 31;
            in_s[c][(yy + 1) * PW + (xx + 1)] = gb[(size_t)(c0 + c) * NX + p];
        }
        for (int idx = tid; idx < OCB * CI * 9; idx += 256) {
            int o = idx / (CI * 9), rem = idx % (CI * 9);
            int c = rem / 9, k = rem % 9;
            float w = Wm[((size_t)(ocg * OCB + o) * CC + (c0 + c)) * 9 + k];
            ull wp; PACK_DUP(wp, w);
            w2_s[o][c][k] = wp;
        }
        __syncthreads();

        if (active) {
            #pragma unroll
            for (int c = 0; c < CI; c++) {
                float nb[3][6];
                #pragma unroll
                for (int dy = 0; dy < 3; dy++)
                    #pragma unroll
                    for (int dx = 0; dx < 6; dx++)
                        nb[dy][dx] = (x0 + dx <= PW - 1)
                                   ? in_s[c][(y + dy) * PW + (x0 + dx)] : 0.f;
                ull nb2[3][3][2];
                #pragma unroll
                for (int dy = 0; dy < 3; dy++)
                    #pragma unroll
                    for (int dx = 0; dx < 3; dx++) {
                        PACK2(nb2[dy][dx][0], nb[dy][dx + 0], nb[dy][dx + 1]);
                        PACK2(nb2[dy][dx][1], nb[dy][dx + 2], nb[dy][dx + 3]);
                    }
                #pragma unroll
                for (int o = 0; o < OCB; o++) {
                    #pragma unroll
                    for (int dy = 0; dy < 3; dy++)
                        #pragma unroll
                        for (int dx = 0; dx < 3; dx++) {
                            ull wp = w2_s[o][c][dy * 3 + dx];
                            FMA_X2(acc2[o][0], nb2[dy][dx][0], wp);
                            FMA_X2(acc2[o][1], nb2[dy][dx][1], wp);
                        }
                }
            }
        }
        __syncthreads();
    }

    if (active) {
        float a = pa[0];
        #pragma unroll
        for (int o = 0; o < OCB; o++) {
            int oc = ocg * OCB + o;
            float s = mg[oc] * rsqrtf(mv[oc] + EPSB);
            float sh = mb[oc] - mm[oc] * s;
            float av[4];
            UNPACK2(av[0], av[1], acc2[o][0]);
            UNPACK2(av[2], av[3], acc2[o][1]);
            #pragma unroll
            for (int p = 0; p < 4; p++) {
                int x = x0 + p;
                if (x < 31) {
                    float v = (av[p] + bm[oc]) * s + sh;
                    v = (v >= 0.f) ? v : a * v;
                    e[(size_t)b * CM * NX + (size_t)oc * NX + (y * 31 + x)] = v;
                }
            }
        }
    }
}

// ---- tiled transpose gat->gatT; blocks (z==0,y==0) also zero colcnt ----
__global__ void transpose_kernel(const float* __restrict__ in, float* __restrict__ outT,
                                 int* __restrict__ cnt)
{
    __shared__ float tile[32][33];
    int b = blockIdx.z;
    int n0 = blockIdx.x * 32;
    int c0 = blockIdx.y * 32;
    int lx = threadIdx.x, ly = threadIdx.y;
    if (blockIdx.z == 0 && blockIdx.y == 0) {
        int base = blockIdx.x * 256 + ly * 32 + lx;
        for (int i = base; i < BATCH * NX; i += 31 * 256) cnt[i] = 0;
    }
    #pragma unroll
    for (int r = 0; r < 4; r++) {
        int c = c0 + ly + r * 8, n = n0 + lx;
        if (n < NX) tile[ly + r * 8][lx] = in[((size_t)b * CC + c) * NX + n];
    }
    __syncthreads();
    #pragma unroll
    for (int r = 0; r < 4; r++) {
        int n = n0 + ly + r * 8, c = c0 + lx;
        if (n < NX) outT[((size_t)b * NX + n) * CC + c] = tile[lx][ly + r * 8];
    }
}

// ---------------- sparsemax + scatter nonzeros to packed column lists ------
__global__ void sparsemax_scatter_kernel(const float* __restrict__ S,
                                         float2* __restrict__ colpk,
                                         int*    __restrict__ colcnt,
                                         int rows)
{
    int warp = (blockIdx.x * blockDim.x + threadIdx.x) >> 5;
    int lane = threadIdx.x & 31;
    if (warp >= rows) return;
    const float* row = S + (size_t)warp * SPAD;
    int b = warp / NX;
    int n = warp - b * NX;

    float v[31];
    #pragma unroll
    for (int t = 0; t < 31; t++) {
        int idx = lane + 32 * t;
        v[t] = (idx < NX) ? row[idx] : -INFINITY;
    }
    float mx = -INFINITY;
    #pragma unroll
    for (int t = 0; t < 31; t++) mx = fmaxf(mx, v[t]);
    #pragma unroll
    for (int o = 16; o; o >>= 1) mx = fmaxf(mx, __shfl_xor_sync(0xFFFFFFFFu, mx, o));
    #pragma unroll
    for (int t = 0; t < 31; t++) v[t] -= mx;

    float lo = -1.f, hi = 0.f;
    for (int it = 0; it < 26; it++) {
        float mid = 0.5f * (lo + hi);
        float f = 0.f;
        #pragma unroll
        for (int t = 0; t < 31; t++) f += fmaxf(v[t] - mid, 0.f);
        #pragma unroll
        for (int o = 16; o; o >>= 1) f += __shfl_xor_sync(0xFFFFFFFFu, f, o);
        if (f >= 1.f) lo = mid; else hi = mid;
    }
    float tm = 0.5f * (lo + hi);
    float cnt = 0.f, sm = 0.f;
    #pragma unroll
    for (int t = 0; t < 31; t++) {
        if (v[t] > tm) { cnt += 1.f; sm += v[t]; }
    }
    #pragma unroll
    for (int o = 16; o; o >>= 1) {
        cnt += __shfl_xor_sync(0xFFFFFFFFu, cnt, o);
        sm  += __shfl_xor_sync(0xFFFFFFFFu, sm,  o);
    }
    float tau = (sm - 1.f) / cnt;

    #pragma unroll
    for (int t = 0; t < 31; t++) {
        int idx = lane + 32 * t;
        if (idx < NX) {
            float p = v[t] - tau;
            if (p > 0.f) {
                int col = b * NX + idx;
                int slot = atomicAdd(&colcnt[col], 1);
                colpk[(size_t)col * NX + slot] = make_float2(p, __int_as_float(n));
            }
        }
    }
}

// ---- sparse out: out[b,:,m] = gat[b,:,m] + sum_n p * gat[b,:,n] ----
#define MCOLS 32
__global__ __launch_bounds__(256, 4)
void sparse_out_kernel(const float* __restrict__ gatT,
                       const float2* __restrict__ colpk,
                       const int*    __restrict__ colcnt,
                       float* __restrict__ out)
{
    int b  = blockIdx.y;
    int m0 = blockIdx.x * MCOLS;
    int tid = threadIdx.x;
    __shared__ float accs[MCOLS][257];

    const float* gT = gatT + (size_t)b * NX * CC;

    for (int mi = 0; mi < MCOLS; mi++) {
        int m = m0 + mi;
        if (m >= NX) break;
        float acc = gT[(size_t)m * CC + tid];
        int cnt = colcnt[b * NX + m];
        const float2* pk = colpk + (size_t)(b * NX + m) * NX;
        int s = 0;
        for (; s + 4 <= cnt; s += 4) {
            float2 q0 = pk[s], q1 = pk[s + 1], q2 = pk[s + 2], q3 = pk[s + 3];
            float v0 = gT[(size_t)__float_as_int(q0.y) * CC + tid];
            float v1 = gT[(size_t)__float_as_int(q1.y) * CC + tid];
            float v2 = gT[(size_t)__float_as_int(q2.y) * CC + tid];
            float v3 = gT[(size_t)__float_as_int(q3.y) * CC + tid];
            acc += q0.x * v0;
            acc += q1.x * v1;
            acc += q2.x * v2;
            acc += q3.x * v3;
        }
        for (; s < cnt; s++) {
            float2 q = pk[s];
            acc += q.x * gT[(size_t)__float_as_int(q.y) * CC + tid];
        }
        accs[mi][tid] = acc;
    }
    __syncthreads();

    #pragma unroll
    for (int r = 0; r < MCOLS; r++) {
        int idx = tid + r * 256;
        int c = idx >> 5, mi = idx & 31;
        int m = m0 + mi;
        if (m < NX)
            out[((size_t)b * CC + c) * NX + m] = accs[mi][c];
    }
}

// ---------------- launch (fork-join on a second stream) ----------------
extern "C" void kernel_launch(void* const* d_in, const int* in_sizes, int n_in,
                              void* d_out, int out_size)
{
    const float* zf  = (const float*)d_in[0];
    const float* xf  = (const float*)d_in[1];
    const float* Wq  = (const float*)d_in[2];
    const float* bq  = (const float*)d_in[3];
    const float* Ws  = (const float*)d_in[4];
    const float* bs  = (const float*)d_in[5];
    const float* Wg  = (const float*)d_in[6];
    const float* bg  = (const float*)d_in[7];
    const float* g_gamma = (const float*)d_in[8];
    const float* g_beta  = (const float*)d_in[9];
    const float* g_mean  = (const float*)d_in[10];
    const float* g_var   = (const float*)d_in[11];
    const float* Wfi = (const float*)d_in[12];
    const float* bfi = (const float*)d_in[13];
    const float* fi_gamma = (const float*)d_in[14];
    const float* fi_beta  = (const float*)d_in[15];
    const float* fi_mean  = (const float*)d_in[16];
    const float* fi_var   = (const float*)d_in[17];
    const float* Wm  = (const float*)d_in[18];
    const float* bm  = (const float*)d_in[19];
    const float* m_gamma = (const float*)d_in[20];
    const float* m_beta  = (const float*)d_in[21];
    const float* m_mean  = (const float*)d_in[22];
    const float* m_var   = (const float*)d_in[23];
    const float* prelu_a = (const float*)d_in[24];
    float* out = (float*)d_out;

    float *xf_g, *zf_t, *zf_g, *tp, *u, *r, *sim, *simT, *gat, *gatT, *e, *S;
    float2 *colpk; int *colcnt;
    cudaGetSymbolAddress((void**)&xf_g, g_xf_g);
    cudaGetSymbolAddress((void**)&zf_t, g_zf_t);
    cudaGetSymbolAddress((void**)&zf_g, g_zf_g);
    cudaGetSymbolAddress((void**)&tp,   g_tp);
    cudaGetSymbolAddress((void**)&u,    g_u);
    cudaGetSymbolAddress((void**)&r,    g_r);
    cudaGetSymbolAddress((void**)&sim,  g_sim);
    cudaGetSymbolAddress((void**)&simT, g_simT);
    cudaGetSymbolAddress((void**)&gat,  g_gat);
    cudaGetSymbolAddress((void**)&gatT, g_gatT);
    cudaGetSymbolAddress((void**)&e,    g_e);
    cudaGetSymbolAddress((void**)&S,    g_S);
    cudaGetSymbolAddress((void**)&colpk, g_colpk);
    cudaGetSymbolAddress((void**)&colcnt, g_colcnt);

    dim3 blk(256);
    const size_t sX  = (size_t)CC * NX;
    const size_t sZ  = (size_t)CC * NZ;
    const size_t sU  = (size_t)CC * UPAD;
    const size_t sSim = (size_t)NX * NZ;
    const size_t sST = (size_t)UPAD * NX;

    SmTask tA = { Ws, 0, CC, 0,  zf, sZ, NZ,  zf_t, sZ, NZ,  CC, NZ, CC, NZ,
                  bs, 0,  nullptr, nullptr, nullptr, nullptr,  nullptr, 0 };
    SmTask tB = { Wg, 0, CC, 0,  zf, sZ, NZ,  zf_g, sZ, NZ,  CC, NZ, CC, NZ,
                  bg, 1,  g_gamma, g_beta, g_mean, g_var,  nullptr, 0 };
    SmTask tD = { Wq, 0, CC, 1,  zf_t, sZ, NZ,  tp, sZ, NZ,  CC, NZ, CC, NZ,
                  nullptr, 0,  nullptr, nullptr, nullptr, nullptr,  nullptr, 0 };
    SmTask tE = { Wfi, 0, 2 * CC, 0,  zf_g, sZ, NZ,  u, sU, UPAD,  CC, NZ, CC, UPAD,
                  nullptr, 0,  nullptr, nullptr, nullptr, nullptr,  nullptr, 0 };
    SmTask tG = { xf, sX, NX, 1,  tp, sZ, NZ,  sim, sSim, NZ,  NX, NZ, CC, NZ,
                  nullptr, 3,  nullptr, nullptr, nullptr, nullptr,  r, NZ };

    // Secondary stream + events for fork-join (host objects only; leaked —
    // kernel_launch runs a handful of times, never during graph replay).
    cudaStream_t s2;
    cudaStreamCreateWithFlags(&s2, cudaStreamNonBlocking);
    cudaEvent_t evForkF, evJoinF, evForkJ, evJoinJ;
    cudaEventCreateWithFlags(&evForkF, cudaEventDisableTiming);
    cudaEventCreateWithFlags(&evJoinF, cudaEventDisableTiming);
    cudaEventCreateWithFlags(&evForkJ, cudaEventDisableTiming);
    cudaEventCreateWithFlags(&evJoinJ, cudaEventDisableTiming);

    // ---- fork: F (xf_g) on s2, independent of the z-side chain ----
    cudaEventRecord(evForkF, 0);
    cudaStreamWaitEvent(s2, evForkF, 0);
    gemm128f_kernel<<<dim3(8, 2, BATCH), blk, 0, s2>>>(
        Wg, 0, CC,  nullptr, 0, 0,
        xf, sX, NX,  nullptr, 0, 0,  -1,
        xf_g, sX, NX,  CC, NX, CC,  bg, 1,
        g_gamma, g_beta, g_mean, g_var);
    cudaEventRecord(evJoinF, s2);

    // ---- main stream: z-side chain ----
    // A+B) zf_t and zf_g
    gemm_sm_dual<<<dim3(1, 16, BATCH), 128>>>(tA, tB, 8);
    // C) r
    rvec_kernel<<<BATCH, 64>>>(zf_t, bq, r);
    // D+E) t' and u (u zero-padded to 64 cols)
    gemm_sm_dual<<<dim3(1, 16, BATCH), 128>>>(tD, tE, 8);
    // G) sim = xf^T t' + r
    gemm_sm_dual<<<dim3(1, 31, BATCH), 128>>>(tG, tG, 0);
    // H) softmax -> attn^T (rows 49..63 zeroed)
    softmax49_kernel<<<(BATCH * NX + 7) / 8, blk>>>(sim, simT, BATCH * NX);

    // ---- join: I needs xf_g (s2) + simT/u (main) ----
    cudaStreamWaitEvent(0, evJoinF, 0);
    // I) gat = relu(bn([u|Wfi_R]*[attn^T; xf_g] + bfi)), K=320, ksplit=64
    gemm128f_kernel<<<dim3(8, 2, BATCH), blk>>>(
        u, sU, UPAD,  Wfi + CC, 0, 2 * CC,
        simT, sST, NX,  xf_g, sX, NX,  UPAD,
        gat, sX, NX,  CC, NX, UPAD + CC,  bfi, 1,
        fi_gamma, fi_beta, fi_mean, fi_var);

    // ---- fork: J (transpose + colcnt zero) on s2, parallel with K, L ----
    cudaEventRecord(evForkJ, 0);
    cudaStreamWaitEvent(s2, evForkJ, 0);
    transpose_kernel<<<dim3(31, 8, BATCH), dim3(32, 8), 0, s2>>>(gat, gatT, colcnt);
    cudaEventRecord(evJoinJ, s2);

    // K) e = prelu(bn(conv3x3(gat) + bm))
    conv3_kernel<<<dim3(BATCH, CM / OCB), blk>>>(
        gat, Wm, bm, m_gamma, m_beta, m_mean, m_var, prelu_a, e);
    // L) S = e^T e, symmetric (36 upper-triangle tile pairs + mirror)
    gemm_symL_kernel<<<dim3(36, 1, BATCH), blk>>>(e, S);

    // ---- join: M needs colcnt (s2) + S (main) ----
    cudaStreamWaitEvent(0, evJoinJ, 0);
    // M) sparsemax rows of S -> packed sparse column lists
    sparsemax_scatter_kernel<<<(BATCH * NX + 7) / 8, blk>>>(
        S, colpk, colcnt, BATCH * NX);
    // N) out = gat + gat * P (sparse)
    sparse_out_kernel<<<dim3((NX + MCOLS - 1) / MCOLS, BATCH), blk>>>(
        gatT, colpk, colcnt, out);
}

// round 17
// speedup vs baseline: 1.0835x; 1.0088x over previous
#include <cuda_runtime.h>
#include <math.h>

#define BATCH 32
#define CC 256
#define CM 64
#define NX 961
#define NZ 49
#define EPSB 1e-5f
#define SPAD 976     // padded leading dim of S (16-float aligned)
#define UPAD 64      // padded K-prefix (u cols / attn^T rows)

typedef unsigned long long ull;

#define FMA_X2(d, a, b) \
    asm("fma.rn.f32x2 %0, %1, %2, %0;" : "+l"(d) : "l"(a), "l"(b))
#define PACK_DUP(d, f) \
    asm("mov.b64 %0, {%1, %1};" : "=l"(d) : "f"(f))
#define PACK2(d, flo, fhi) \
    asm("mov.b64 %0, {%1, %2};" : "=l"(d) : "f"(flo), "f"(fhi))
#define UNPACK2(flo, fhi, s) \
    asm("mov.b64 {%0, %1}, %2;" : "=f"(flo), "=f"(fhi) : "l"(s))

// ---------------- scratch (device globals; no allocation) ----------------
__device__ float g_xf_g[BATCH * CC * NX];
__device__ float g_zf_t[BATCH * CC * NZ];
__device__ float g_zf_g[BATCH * CC * NZ];
__device__ float g_tp  [BATCH * CC * NZ];    // t' = Wq^T zf_t
__device__ float g_u   [BATCH * CC * UPAD];  // u = Wfi_left zf_g (cols 49..63 = 0)
__device__ float g_r   [BATCH * NZ];
__device__ float g_simT[BATCH * UPAD * NX];  // attn^T, rows 49..63 = 0
__device__ float g_gat [BATCH * CC * NX];
__device__ float g_gatT[BATCH * NX * CC];
__device__ float g_e   [BATCH * CM * NX];
__device__ float g_S   [(size_t)BATCH * NX * SPAD];
__device__ float2 g_colpk[(size_t)BATCH * NX * NX];
__device__ int   g_colcnt[BATCH * NX];

// ============ 128x128 fp32 GEMM: double-buffered smem, concat ====
// Requires K % 16 == 0 and (ksplit < 0 or ksplit % 16 == 0).
#define GM 128
#define GN 128
#define GK 16
#define GPAD 132

__global__ __launch_bounds__(256, 2)
void gemm128f_kernel(
    const float* __restrict__ A, size_t sAb, int lda,
    const float* __restrict__ A2, size_t sA2b, int lda2,
    const float* __restrict__ B, size_t sBb, int ldb,
    const float* __restrict__ B2, size_t sB2b, int ldb2,
    int ksplit,
    float* __restrict__ Cout, size_t sCb, int ldc,
    int M, int N, int K,
    const float* __restrict__ bias, int epi,
    const float* __restrict__ gamma, const float* __restrict__ beta,
    const float* __restrict__ mean,  const float* __restrict__ var)
{
    __shared__ float As[2][GK][GPAD];
    __shared__ float Bs[2][GK][GPAD];

    int b = blockIdx.z;
    const float* Ab  = A + (size_t)b * sAb;
    const float* A2b = A2 ? (A2 + (size_t)b * sA2b) : nullptr;
    const float* Bb  = B + (size_t)b * sBb;
    const float* B2b = B2 ? (B2 + (size_t)b * sB2b) : nullptr;
    float* Cb = Cout + (size_t)b * sCb;

    int m0 = blockIdx.y * GM;
    int n0 = blockIdx.x * GN;
    int tid = threadIdx.x;
    int tx = tid & 15, ty = tid >> 4;

    int kA = tid & 15;
    int lmA[8]; bool vA[8];
    #pragma unroll
    for (int r = 0; r < 8; r++) {
        lmA[r] = (tid >> 4) + r * 16;
        vA[r] = (m0 + lmA[r]) < M;
    }
    int nB = tid & 127;
    bool vB = (n0 + nB) < N;
    int kB0 = tid >> 7;

    ull acc2[8][4] = {};
    float pa[8], pb[8];

    auto load_tiles = [&](int k0) {
        const float* Asrc; int ald;
        const float* Bsrc; int bld;
        if (ksplit >= 0 && k0 >= ksplit) {
            Asrc = A2b + (k0 - ksplit); ald = lda2;
            Bsrc = B2b + (size_t)(k0 - ksplit) * ldb2; bld = ldb2;
        } else {
            Asrc = Ab + k0; ald = lda;
            Bsrc = Bb + (size_t)k0 * ldb; bld = ldb;
        }
        #pragma unroll
        for (int r = 0; r < 8; r++)
            pa[r] = vA[r] ? Asrc[(size_t)(m0 + lmA[r]) * ald + kA] : 0.f;
        const float* Bp = Bsrc + (size_t)kB0 * bld + (n0 + nB);
        #pragma unroll
        for (int r = 0; r < 8; r++)
            pb[r] = vB ? Bp[(size_t)(2 * r) * bld] : 0.f;
    };
    auto store_tiles = [&](int buf) {
        #pragma unroll
        for (int r = 0; r < 8; r++) As[buf][kA][lmA[r]] = pa[r];
        #pragma unroll
        for (int r = 0; r < 8; r++) Bs[buf][kB0 + 2 * r][nB] = pb[r];
    };
    auto compute = [&](int buf) {
        #pragma unroll
        for (int k = 0; k < GK; k++) {
            float4 a0 = *reinterpret_cast<const float4*>(&As[buf][k][ty * 4]);
            float4 a1 = *reinterpret_cast<const float4*>(&As[buf][k][ty * 4 + 64]);
            ulonglong2 b01 = *reinterpret_cast<const ulonglong2*>(&Bs[buf][k][tx * 4]);
            ulonglong2 b23 = *reinterpret_cast<const ulonglong2*>(&Bs[buf][k][tx * 4 + 64]);
            float am[8] = {a0.x, a0.y, a0.z, a0.w, a1.x, a1.y, a1.z, a1.w};
            ull bp[4] = {b01.x, b01.y, b23.x, b23.y};
            #pragma unroll
            for (int i = 0; i < 8; i++) {
                ull ap;
                PACK_DUP(ap, am[i]);
                #pragma unroll
                for (int jp = 0; jp < 4; jp++)
                    FMA_X2(acc2[i][jp], ap, bp[jp]);
            }
        }
    };

    load_tiles(0);
    store_tiles(0);
    __syncthreads();

    int nk = K / GK;
    for (int it = 0; it < nk; it++) {
        bool more = (it + 1) < nk;
        if (more) load_tiles((it + 1) * GK);
        compute(it & 1);
        if (more) { store_tiles((it + 1) & 1); __syncthreads(); }
    }

    #pragma unroll
    for (int i = 0; i < 8; i++) {
        int m = m0 + ty * 4 + (i & 3) + ((i >> 2) << 6);
        if (m >= M) continue;
        float bval = bias ? bias[m] : 0.f;
        float s = 1.f, sh = 0.f;
        if (epi == 1) {
            s = gamma[m] * rsqrtf(var[m] + EPSB);
            sh = beta[m] - mean[m] * s;
        }
        #pragma unroll
        for (int jp = 0; jp < 4; jp++) {
            float vlo, vhi;
            UNPACK2(vlo, vhi, acc2[i][jp]);
            float vv[2] = {vlo, vhi};
            #pragma unroll
            for (int h = 0; h < 2; h++) {
                int n = n0 + tx * 4 + ((jp & 1) << 1) + h + ((jp >> 1) << 6);
                if (n >= N) continue;
                float v = vv[h] + bval;
                if (epi == 1) v = fmaxf(v * s + sh, 0.f);
                Cb[(size_t)m * ldc + n] = v;
            }
        }
    }
}

// ============ symmetric S = e^T e: double-buffered, mirror ============
__global__ __launch_bounds__(256, 2)
void gemm_symL_kernel(const float* __restrict__ e, float* __restrict__ S)
{
    __shared__ float As[2][GK][GPAD];
    __shared__ float Bs[2][GK][GPAD];

    int b = blockIdx.z;
    const float* E = e + (size_t)b * CM * NX;
    float* Sb = S + (size_t)b * NX * SPAD;

    int lin = blockIdx.x, i = 0;
    while (lin >= 8 - i) { lin -= 8 - i; i++; }
    int j = i + lin;
    int m0 = i * 128, n0 = j * 128;

    int tid = threadIdx.x, tx = tid & 15, ty = tid >> 4;
    int mn = tid & 127;
    int kk = tid >> 7;
    bool vA = (m0 + mn) < NX;
    bool vB = (n0 + mn) < NX;

    ull acc2[8][4] = {};
    float pa[8], pb[8];

    auto load_tiles = [&](int k0) {
        const float* Ea = E + (size_t)(k0 + kk) * NX;
        #pragma unroll
        for (int r = 0; r < 8; r++) {
            const float* Er = Ea + (size_t)(2 * r) * NX;
            pa[r] = vA ? Er[m0 + mn] : 0.f;
            pb[r] = vB ? Er[n0 + mn] : 0.f;
        }
    };
    auto store_tiles = [&](int buf) {
        #pragma unroll
        for (int r = 0; r < 8; r++) {
            As[buf][kk + 2 * r][mn] = pa[r];
            Bs[buf][kk + 2 * r][mn] = pb[r];
        }
    };
    auto compute = [&](int buf) {
        #pragma unroll
        for (int k = 0; k < GK; k++) {
            float4 a0 = *reinterpret_cast<const float4*>(&As[buf][k][ty * 4]);
            float4 a1 = *reinterpret_cast<const float4*>(&As[buf][k][ty * 4 + 64]);
            ulonglong2 b01 = *reinterpret_cast<const ulonglong2*>(&Bs[buf][k][tx * 4]);
            ulonglong2 b23 = *reinterpret_cast<const ulonglong2*>(&Bs[buf][k][tx * 4 + 64]);
            float am[8] = {a0.x, a0.y, a0.z, a0.w, a1.x, a1.y, a1.z, a1.w};
            ull bp[4] = {b01.x, b01.y, b23.x, b23.y};
            #pragma unroll
            for (int ii = 0; ii < 8; ii++) {
                ull ap;
                PACK_DUP(ap, am[ii]);
                #pragma unroll
                for (int jp = 0; jp < 4; jp++)
                    FMA_X2(acc2[ii][jp], ap, bp[jp]);
            }
        }
    };

    load_tiles(0);
    store_tiles(0);
    __syncthreads();

    const int nk = CM / GK;   // 4
    for (int it = 0; it < nk; it++) {
        bool more = (it + 1) < nk;
        if (more) load_tiles((it + 1) * GK);
        compute(it & 1);
        if (more) { store_tiles((it + 1) & 1); __syncthreads(); }
    }

    float acc[8][8];
    #pragma unroll
    for (int ii = 0; ii < 8; ii++)
        #pragma unroll
        for (int jp = 0; jp < 4; jp++)
            UNPACK2(acc[ii][jp * 2], acc[ii][jp * 2 + 1], acc2[ii][jp]);

    #pragma unroll
    for (int ii = 0; ii < 8; ii++) {
        int m = m0 + ty * 4 + (ii & 3) + ((ii >> 2) << 6);
        if (m >= NX) continue;
        #pragma unroll
        for (int jp = 0; jp < 4; jp++)
            #pragma unroll
            for (int h = 0; h < 2; h++) {
                int n = n0 + tx * 4 + ((jp & 1) << 1) + h + ((jp >> 1) << 6);
                if (n < NX) Sb[(size_t)m * SPAD + n] = acc[ii][jp * 2 + h];
            }
    }
    if (i != j) {
        #pragma unroll
        for (int jp = 0; jp < 4; jp++)
            #pragma unroll
            for (int h = 0; h < 2; h++) {
                int n = n0 + tx * 4 + ((jp & 1) << 1) + h + ((jp >> 1) << 6);
                if (n >= NX) continue;
                float4 v0 = make_float4(acc[0][jp * 2 + h], acc[1][jp * 2 + h],
                                        acc[2][jp * 2 + h], acc[3][jp * 2 + h]);
                float4 v1 = make_float4(acc[4][jp * 2 + h], acc[5][jp * 2 + h],
                                        acc[6][jp * 2 + h], acc[7][jp * 2 + h]);
                *reinterpret_cast<float4*>(&Sb[(size_t)n * SPAD + m0 + ty * 4]) = v0;
                *reinterpret_cast<float4*>(&Sb[(size_t)n * SPAD + m0 + 64 + ty * 4]) = v1;
            }
    }
}

// ====== small GEMM: 32x64 tile, 128 threads, double-buffered ======
struct SmTask {
    const float* A; size_t sAb; int lda; int aT;
    const float* B; size_t sBb; int ldb;
    float* C; size_t sCb; int ldc;
    int M, N, K, Npad;
    const float* bias; int epi;
    const float* gamma; const float* beta; const float* mean; const float* var;
};

#define SBK 16
__global__ __launch_bounds__(128)
void gemm_sm_dual(SmTask t0, SmTask t1, int split)
{
    int by = blockIdx.y;
    bool second = (split > 0 && by >= split);
    const SmTask& t = second ? t1 : t0;
    int mt = second ? by - split : by;

    int b = blockIdx.z;
    const float* Ab = t.A + (size_t)b * t.sAb;
    const float* Bb = t.B + (size_t)b * t.sBb;
    float* Cb = t.C + (size_t)b * t.sCb;

    __shared__ float As[2][SBK][32];
    __shared__ float Bs[2][SBK][64];

    int tid = threadIdx.x;
    int tx = tid & 15, ty = tid >> 4;
    int m0 = mt * 32;

    ull acc2[4][2] = {};
    float pa[4], pb[8];

    auto load_t = [&](int k0) {
        if (!t.aT) {
            #pragma unroll
            for (int r = 0; r < 4; r++) {
                int idx = tid + r * 128;
                int tk = idx & 15, tm = idx >> 4;
                int gm = m0 + tm, gk = k0 + tk;
                pa[r] = (gm < t.M && gk < t.K) ? Ab[(size_t)gm * t.lda + gk] : 0.f;
            }
        } else {
            #pragma unroll
            for (int r = 0; r < 4; r++) {
                int idx = tid + r * 128;
                int tm = idx & 31, tk = idx >> 5;
                int gm = m0 + tm, gk = k0 + tk;
                pa[r] = (gm < t.M && gk < t.K) ? Ab[(size_t)gk * t.lda + gm] : 0.f;
            }
        }
        #pragma unroll
        for (int r = 0; r < 8; r++) {
            int idx = tid + r * 128;
            int tn = idx & 63, tk = idx >> 6;
            int gk = k0 + tk;
            pb[r] = (tn < t.N && gk < t.K) ? Bb[(size_t)gk * t.ldb + tn] : 0.f;
        }
    };
    auto store_t = [&](int buf) {
        if (!t.aT) {
            #pragma unroll
            for (int r = 0; r < 4; r++) {
                int idx = tid + r * 128;
                As[buf][idx & 15][idx >> 4] = pa[r];
            }
        } else {
            #pragma unroll
            for (int r = 0; r < 4; r++) {
                int idx = tid + r * 128;
                As[buf][idx >> 5][idx & 31] = pa[r];
            }
        }
        #pragma unroll
        for (int r = 0; r < 8; r++) {
            int idx = tid + r * 128;
            Bs[buf][idx >> 6][idx & 63] = pb[r];
        }
    };
    auto compute = [&](int buf) {
        #pragma unroll
        for (int k = 0; k < SBK; k++) {
            float4 av = *reinterpret_cast<const float4*>(&As[buf][k][ty * 4]);
            ulonglong2 bv = *reinterpret_cast<const ulonglong2*>(&Bs[buf][k][tx * 4]);
            float a4[4] = {av.x, av.y, av.z, av.w};
            ull bp[2] = {bv.x, bv.y};
            #pragma unroll
            for (int i = 0; i < 4; i++) {
                ull ap;
                PACK_DUP(ap, a4[i]);
                #pragma unroll
                for (int jp = 0; jp < 2; jp++)
                    FMA_X2(acc2[i][jp], ap, bp[jp]);
            }
        }
    };

    load_t(0);
    store_t(0);
    __syncthreads();

    int nk = (t.K + SBK - 1) / SBK;
    for (int it = 0; it < nk; it++) {
        bool more = (it + 1) < nk;
        if (more) load_t((it + 1) * SBK);
        compute(it & 1);
        if (more) { store_t((it + 1) & 1); __syncthreads(); }
    }

    #pragma unroll
    for (int i = 0; i < 4; i++) {
        int m = m0 + ty * 4 + i;
        if (m >= t.M) continue;
        float bval = t.bias ? t.bias[m] : 0.f;
        float s = 1.f, sh = 0.f;
        if (t.epi == 1) {
            s = t.gamma[m] * rsqrtf(t.var[m] + EPSB);
            sh = t.beta[m] - t.mean[m] * s;
        }
        #pragma unroll
        for (int jp = 0; jp < 2; jp++) {
            float vlo, vhi;
            UNPACK2(vlo, vhi, acc2[i][jp]);
            float vv[2] = {vlo, vhi};
            #pragma unroll
            for (int h = 0; h < 2; h++) {
                int n = tx * 4 + jp * 2 + h;
                if (n >= t.Npad) continue;
                float v;
                if (n >= t.N) {
                    v = 0.f;
                } else {
                    v = vv[h] + bval;
                    if (t.epi == 1) v = fmaxf(v * s + sh, 0.f);
                }
                Cb[(size_t)m * t.ldc + n] = v;
            }
        }
    }
}

// ====== G fused: sim = xf^T tp + r, then row-softmax -> simT (attn^T) ======
// 32 rows per block (grid.y = 31), N=49 complete per block, K=256.
__global__ __launch_bounds__(128)
void gemm_simG_kernel(const float* __restrict__ xf, const float* __restrict__ tp,
                      const float* __restrict__ r, float* __restrict__ simT)
{
    int b = blockIdx.z;
    int m0 = blockIdx.y * 32;
    const float* Ab = xf + (size_t)b * CC * NX;   // A[k][m]
    const float* Bb = tp + (size_t)b * CC * NZ;   // B[k][n]
    const float* rb = r + (size_t)b * NZ;
    float* STb = simT + (size_t)b * UPAD * NX;

    __shared__ float As[2][SBK][32];
    __shared__ float Bs[2][SBK][64];

    int tid = threadIdx.x;
    int tx = tid & 15, ty = tid >> 4;

    ull acc2[4][2] = {};
    float pa[4], pb[8];

    auto load_t = [&](int k0) {
        #pragma unroll
        for (int rr = 0; rr < 4; rr++) {
            int idx = tid + rr * 128;
            int tm = idx & 31, tk = idx >> 5;
            int gm = m0 + tm;
            pa[rr] = (gm < NX) ? Ab[(size_t)(k0 + tk) * NX + gm] : 0.f;
        }
        #pragma unroll
        for (int rr = 0; rr < 8; rr++) {
            int idx = tid + rr * 128;
            int tn = idx & 63, tk = idx >> 6;
            pb[rr] = (tn < NZ) ? Bb[(size_t)(k0 + tk) * NZ + tn] : 0.f;
        }
    };
    auto store_t = [&](int buf) {
        #pragma unroll
        for (int rr = 0; rr < 4; rr++) {
            int idx = tid + rr * 128;
            As[buf][idx >> 5][idx & 31] = pa[rr];
        }
        #pragma unroll
        for (int rr = 0; rr < 8; rr++) {
            int idx = tid + rr * 128;
            Bs[buf][idx >> 6][idx & 63] = pb[rr];
        }
    };
    auto compute = [&](int buf) {
        #pragma unroll
        for (int k = 0; k < SBK; k++) {
            float4 av = *reinterpret_cast<const float4*>(&As[buf][k][ty * 4]);
            ulonglong2 bv = *reinterpret_cast<const ulonglong2*>(&Bs[buf][k][tx * 4]);
            float a4[4] = {av.x, av.y, av.z, av.w};
            ull bp[2] = {bv.x, bv.y};
            #pragma unroll
            for (int i = 0; i < 4; i++) {
                ull ap;
                PACK_DUP(ap, a4[i]);
                #pragma unroll
                for (int jp = 0; jp < 2; jp++)
                    FMA_X2(acc2[i][jp], ap, bp[jp]);
            }
        }
    };

    load_t(0);
    store_t(0);
    __syncthreads();

    const int nk = CC / SBK;  // 16
    for (int it = 0; it < nk; it++) {
        bool more = (it + 1) < nk;
        if (more) load_t((it + 1) * SBK);
        compute(it & 1);
        if (more) { store_t((it + 1) & 1); __syncthreads(); }
    }

    // epilogue: per row m, softmax over n=0..48; write attn^T (rows 49..63 = 0)
    int nbase = tx * 4;
    float rv[4];
    #pragma unroll
    for (int s = 0; s < 4; s++) {
        int n = nbase + s;
        rv[s] = (n < NZ) ? rb[n] : 0.f;
    }
    #pragma unroll
    for (int i = 0; i < 4; i++) {
        int m = m0 + ty * 4 + i;
        float vv[4];
        {
            float vlo, vhi;
            UNPACK2(vlo, vhi, acc2[i][0]); vv[0] = vlo + rv[0]; vv[1] = vhi + rv[1];
            UNPACK2(vlo, vhi, acc2[i][1]); vv[2] = vlo + rv[2]; vv[3] = vhi + rv[3];
        }
        float mx = -INFINITY;
        #pragma unroll
        for (int s = 0; s < 4; s++)
            if (nbase + s < NZ) mx = fmaxf(mx, vv[s]);
        #pragma unroll
        for (int o = 8; o; o >>= 1) mx = fmaxf(mx, __shfl_xor_sync(0xFFFFFFFFu, mx, o));
        float ex[4];
        float sum = 0.f;
        #pragma unroll
        for (int s = 0; s < 4; s++) {
            ex[s] = (nbase + s < NZ) ? expf(vv[s] - mx) : 0.f;
            sum += ex[s];
        }
        #pragma unroll
        for (int o = 8; o; o >>= 1) sum += __shfl_xor_sync(0xFFFFFFFFu, sum, o);
        float inv = 1.f / sum;
        if (m < NX) {
            #pragma unroll
            for (int s = 0; s < 4; s++) {
                int n = nbase + s;
                STb[(size_t)n * NX + m] = (n < NZ) ? ex[s] * inv : 0.f;
            }
        }
    }
}

// ---------------- r[b][m] = bq . zf_t[b][:,m] ----------------
__global__ void rvec_kernel(const float* __restrict__ zf_t,
                            const float* __restrict__ bq,
                            float* __restrict__ r)
{
    int b = blockIdx.x;
    int m = threadIdx.x;
    if (m >= NZ) return;
    const float* z = zf_t + (size_t)b * CC * NZ;
    float acc = 0.f;
    for (int c = 0; c < CC; c++)
        acc += bq[c] * z[(size_t)c * NZ + m];
    r[b * NZ + m] = acc;
}

// ---------------- conv3x3 + BN + PReLU (FFMA2, OCB=8) --------
#define CI 8
#define OCB 8
#define PW 33

__global__ __launch_bounds__(256, 2)
void conv3_kernel(const float* __restrict__ gat, const float* __restrict__ Wm,
                  const float* __restrict__ bm,
                  const float* __restrict__ mg, const float* __restrict__ mb,
                  const float* __restrict__ mm, const float* __restrict__ mv,
                  const float* __restrict__ pa,
                  float* __restrict__ e)
{
    int b = blockIdx.x;
    int ocg = blockIdx.y;
    __shared__ float in_s[CI][PW * PW];
    __shared__ ull   w2_s[OCB][CI][9];
    int tid = threadIdx.x;

    for (int idx = tid; idx < CI * PW * PW; idx += 256)
        (&in_s[0][0])[idx] = 0.f;
    __syncthreads();

    int y  = tid >> 3;
    int x0 = (tid & 7) << 2;
    bool active = (tid < 248);

    ull acc2[OCB][2] = {};
    const float* gb = gat + (size_t)b * CC * NX;

    for (int c0 = 0; c0 < CC; c0 += CI) {
        for (int idx = tid; idx < CI * NX; idx += 256) {
            int c = idx / NX, p = idx - c * NX;
            int yy = p / 31, xx = p - yy * 31;
            in_s[c][(yy + 1) * PW + (xx + 1)] = gb[(size_t)(c0 + c) * NX + p];
        }
        for (int idx = tid; idx < OCB * CI * 9; idx += 256) {
            int o = idx / (CI * 9), rem = idx % (CI * 9);
            int c = rem / 9, k = rem % 9;
            float w = Wm[((size_t)(ocg * OCB + o) * CC + (c0 + c)) * 9 + k];
            ull wp; PACK_DUP(wp, w);
            w2_s[o][c][k] = wp;
        }
        __syncthreads();

        if (active) {
            #pragma unroll
            for (int c = 0; c < CI; c++) {
                float nb[3][6];
                #pragma unroll
                for (int dy = 0; dy < 3; dy++)
                    #pragma unroll
                    for (int dx = 0; dx < 6; dx++)
                        nb[dy][dx] = (x0 + dx <= PW - 1)
                                   ? in_s[c][(y + dy) * PW + (x0 + dx)] : 0.f;
                ull nb2[3][3][2];
                #pragma unroll
                for (int dy = 0; dy < 3; dy++)
                    #pragma unroll
                    for (int dx = 0; dx < 3; dx++) {
                        PACK2(nb2[dy][dx][0], nb[dy][dx + 0], nb[dy][dx + 1]);
                        PACK2(nb2[dy][dx][1], nb[dy][dx + 2], nb[dy][dx + 3]);
                    }
                #pragma unroll
                for (int o = 0; o < OCB; o++) {
                    #pragma unroll
                    for (int dy = 0; dy < 3; dy++)
                        #pragma unroll
                        for (int dx = 0; dx < 3; dx++) {
                            ull wp = w2_s[o][c][dy * 3 + dx];
                            FMA_X2(acc2[o][0], nb2[dy][dx][0], wp);
                            FMA_X2(acc2[o][1], nb2[dy][dx][1], wp);
                        }
                }
            }
        }
        __syncthreads();
    }

    if (active) {
        float a = pa[0];
        #pragma unroll
        for (int o = 0; o < OCB; o++) {
            int oc = ocg * OCB + o;
            float s = mg[oc] * rsqrtf(mv[oc] + EPSB);
            float sh = mb[oc] - mm[oc] * s;
            float av[4];
            UNPACK2(av[0], av[1], acc2[o][0]);
            UNPACK2(av[2], av[3], acc2[o][1]);
            #pragma unroll
            for (int p = 0; p < 4; p++) {
                int x = x0 + p;
                if (x < 31) {
                    float v = (av[p] + bm[oc]) * s + sh;
                    v = (v >= 0.f) ? v : a * v;
                    e[(size_t)b * CM * NX + (size_t)oc * NX + (y * 31 + x)] = v;
                }
            }
        }
    }
}

// ---- tiled transpose gat->gatT; blocks (z==0,y==0) also zero colcnt ----
__global__ void transpose_kernel(const float* __restrict__ in, float* __restrict__ outT,
                                 int* __restrict__ cnt)
{
    __shared__ float tile[32][33];
    int b = blockIdx.z;
    int n0 = blockIdx.x * 32;
    int c0 = blockIdx.y * 32;
    int lx = threadIdx.x, ly = threadIdx.y;
    if (blockIdx.z == 0 && blockIdx.y == 0) {
        int base = blockIdx.x * 256 + ly * 32 + lx;
        for (int i = base; i < BATCH * NX; i += 31 * 256) cnt[i] = 0;
    }
    #pragma unroll
    for (int r = 0; r < 4; r++) {
        int c = c0 + ly + r * 8, n = n0 + lx;
        if (n < NX) tile[ly + r * 8][lx] = in[((size_t)b * CC + c) * NX + n];
    }
    __syncthreads();
    #pragma unroll
    for (int r = 0; r < 4; r++) {
        int n = n0 + ly + r * 8, c = c0 + lx;
        if (n < NX) outT[((size_t)b * NX + n) * CC + c] = tile[lx][ly + r * 8];
    }
}

// ---------------- sparsemax + scatter nonzeros to packed column lists ------
__global__ void sparsemax_scatter_kernel(const float* __restrict__ S,
                                         float2* __restrict__ colpk,
                                         int*    __restrict__ colcnt,
                                         int rows)
{
    int warp = (blockIdx.x * blockDim.x + threadIdx.x) >> 5;
    int lane = threadIdx.x & 31;
    if (warp >= rows) return;
    const float* row = S + (size_t)warp * SPAD;
    int b = warp / NX;
    int n = warp - b * NX;

    float v[31];
    #pragma unroll
    for (int t = 0; t < 31; t++) {
        int idx = lane + 32 * t;
        v[t] = (idx < NX) ? row[idx] : -INFINITY;
    }
    float mx = -INFINITY;
    #pragma unroll
    for (int t = 0; t < 31; t++) mx = fmaxf(mx, v[t]);
    #pragma unroll
    for (int o = 16; o; o >>= 1) mx = fmaxf(mx, __shfl_xor_sync(0xFFFFFFFFu, mx, o));
    #pragma unroll
    for (int t = 0; t < 31; t++) v[t] -= mx;

    float lo = -1.f, hi = 0.f;
    for (int it = 0; it < 26; it++) {
        float mid = 0.5f * (lo + hi);
        float f = 0.f;
        #pragma unroll
        for (int t = 0; t < 31; t++) f += fmaxf(v[t] - mid, 0.f);
        #pragma unroll
        for (int o = 16; o; o >>= 1) f += __shfl_xor_sync(0xFFFFFFFFu, f, o);
        if (f >= 1.f) lo = mid; else hi = mid;
    }
    float tm = 0.5f * (lo + hi);
    float cnt = 0.f, sm = 0.f;
    #pragma unroll
    for (int t = 0; t < 31; t++) {
        if (v[t] > tm) { cnt += 1.f; sm += v[t]; }
    }
    #pragma unroll
    for (int o = 16; o; o >>= 1) {
        cnt += __shfl_xor_sync(0xFFFFFFFFu, cnt, o);
        sm  += __shfl_xor_sync(0xFFFFFFFFu, sm,  o);
    }
    float tau = (sm - 1.f) / cnt;

    #pragma unroll
    for (int t = 0; t < 31; t++) {
        int idx = lane + 32 * t;
        if (idx < NX) {
            float p = v[t] - tau;
            if (p > 0.f) {
                int col = b * NX + idx;
                int slot = atomicAdd(&colcnt[col], 1);
                colpk[(size_t)col * NX + slot] = make_float2(p, __int_as_float(n));
            }
        }
    }
}

// ---- sparse out: out[b,:,m] = gat[b,:,m] + sum_n p * gat[b,:,n] ----
#define MCOLS 32
__global__ __launch_bounds__(256, 4)
void sparse_out_kernel(const float* __restrict__ gatT,
                       const float2* __restrict__ colpk,
                       const int*    __restrict__ colcnt,
                       float* __restrict__ out)
{
    int b  = blockIdx.y;
    int m0 = blockIdx.x * MCOLS;
    int tid = threadIdx.x;
    __shared__ float accs[MCOLS][257];

    const float* gT = gatT + (size_t)b * NX * CC;

    for (int mi = 0; mi < MCOLS; mi++) {
        int m = m0 + mi;
        if (m >= NX) break;
        float acc = gT[(size_t)m * CC + tid];
        int cnt = colcnt[b * NX + m];
        const float2* pk = colpk + (size_t)(b * NX + m) * NX;
        int s = 0;
        for (; s + 4 <= cnt; s += 4) {
            float2 q0 = pk[s], q1 = pk[s + 1], q2 = pk[s + 2], q3 = pk[s + 3];
            float v0 = gT[(size_t)__float_as_int(q0.y) * CC + tid];
            float v1 = gT[(size_t)__float_as_int(q1.y) * CC + tid];
            float v2 = gT[(size_t)__float_as_int(q2.y) * CC + tid];
            float v3 = gT[(size_t)__float_as_int(q3.y) * CC + tid];
            acc += q0.x * v0;
            acc += q1.x * v1;
            acc += q2.x * v2;
            acc += q3.x * v3;
        }
        for (; s < cnt; s++) {
            float2 q = pk[s];
            acc += q.x * gT[(size_t)__float_as_int(q.y) * CC + tid];
        }
        accs[mi][tid] = acc;
    }
    __syncthreads();

    #pragma unroll
    for (int r = 0; r < MCOLS; r++) {
        int idx = tid + r * 256;
        int c = idx >> 5, mi = idx & 31;
        int m = m0 + mi;
        if (m < NX)
            out[((size_t)b * CC + c) * NX + m] = accs[mi][c];
    }
}

// ---------------- launch (fork-join on a second stream) ----------------
extern "C" void kernel_launch(void* const* d_in, const int* in_sizes, int n_in,
                              void* d_out, int out_size)
{
    const float* zf  = (const float*)d_in[0];
    const float* xf  = (const float*)d_in[1];
    const float* Wq  = (const float*)d_in[2];
    const float* bq  = (const float*)d_in[3];
    const float* Ws  = (const float*)d_in[4];
    const float* bs  = (const float*)d_in[5];
    const float* Wg  = (const float*)d_in[6];
    const float* bg  = (const float*)d_in[7];
    const float* g_gamma = (const float*)d_in[8];
    const float* g_beta  = (const float*)d_in[9];
    const float* g_mean  = (const float*)d_in[10];
    const float* g_var   = (const float*)d_in[11];
    const float* Wfi = (const float*)d_in[12];
    const float* bfi = (const float*)d_in[13];
    const float* fi_gamma = (const float*)d_in[14];
    const float* fi_beta  = (const float*)d_in[15];
    const float* fi_mean  = (const float*)d_in[16];
    const float* fi_var   = (const float*)d_in[17];
    const float* Wm  = (const float*)d_in[18];
    const float* bm  = (const float*)d_in[19];
    const float* m_gamma = (const float*)d_in[20];
    const float* m_beta  = (const float*)d_in[21];
    const float* m_mean  = (const float*)d_in[22];
    const float* m_var   = (const float*)d_in[23];
    const float* prelu_a = (const float*)d_in[24];
    float* out = (float*)d_out;

    float *xf_g, *zf_t, *zf_g, *tp, *u, *r, *simT, *gat, *gatT, *e, *S;
    float2 *colpk; int *colcnt;
    cudaGetSymbolAddress((void**)&xf_g, g_xf_g);
    cudaGetSymbolAddress((void**)&zf_t, g_zf_t);
    cudaGetSymbolAddress((void**)&zf_g, g_zf_g);
    cudaGetSymbolAddress((void**)&tp,   g_tp);
    cudaGetSymbolAddress((void**)&u,    g_u);
    cudaGetSymbolAddress((void**)&r,    g_r);
    cudaGetSymbolAddress((void**)&simT, g_simT);
    cudaGetSymbolAddress((void**)&gat,  g_gat);
    cudaGetSymbolAddress((void**)&gatT, g_gatT);
    cudaGetSymbolAddress((void**)&e,    g_e);
    cudaGetSymbolAddress((void**)&S,    g_S);
    cudaGetSymbolAddress((void**)&colpk, g_colpk);
    cudaGetSymbolAddress((void**)&colcnt, g_colcnt);

    dim3 blk(256);
    const size_t sX  = (size_t)CC * NX;
    const size_t sZ  = (size_t)CC * NZ;
    const size_t sU  = (size_t)CC * UPAD;
    const size_t sST = (size_t)UPAD * NX;

    SmTask tA = { Ws, 0, CC, 0,  zf, sZ, NZ,  zf_t, sZ, NZ,  CC, NZ, CC, NZ,
                  bs, 0,  nullptr, nullptr, nullptr, nullptr };
    SmTask tB = { Wg, 0, CC, 0,  zf, sZ, NZ,  zf_g, sZ, NZ,  CC, NZ, CC, NZ,
                  bg, 1,  g_gamma, g_beta, g_mean, g_var };
    SmTask tD = { Wq, 0, CC, 1,  zf_t, sZ, NZ,  tp, sZ, NZ,  CC, NZ, CC, NZ,
                  nullptr, 0,  nullptr, nullptr, nullptr, nullptr };
    SmTask tE = { Wfi, 0, 2 * CC, 0,  zf_g, sZ, NZ,  u, sU, UPAD,  CC, NZ, CC, UPAD,
                  nullptr, 0,  nullptr, nullptr, nullptr, nullptr };

    // Secondary stream + events (host objects only; leaked — kernel_launch
    // runs a handful of times, never during graph replay).
    cudaStream_t s2;
    cudaStreamCreateWithFlags(&s2, cudaStreamNonBlocking);
    cudaEvent_t evForkF, evJoinF, evForkJ, evJoinJ;
    cudaEventCreateWithFlags(&evForkF, cudaEventDisableTiming);
    cudaEventCreateWithFlags(&evJoinF, cudaEventDisableTiming);
    cudaEventCreateWithFlags(&evForkJ, cudaEventDisableTiming);
    cudaEventCreateWithFlags(&evJoinJ, cudaEventDisableTiming);

    // ---- fork: F (xf_g) on s2, independent of the z-side chain ----
    cudaEventRecord(evForkF, 0);
    cudaStreamWaitEvent(s2, evForkF, 0);
    gemm128f_kernel<<<dim3(8, 2, BATCH), blk, 0, s2>>>(
        Wg, 0, CC,  nullptr, 0, 0,
        xf, sX, NX,  nullptr, 0, 0,  -1,
        xf_g, sX, NX,  CC, NX, CC,  bg, 1,
        g_gamma, g_beta, g_mean, g_var);
    cudaEventRecord(evJoinF, s2);

    // ---- main stream: z-side chain ----
    gemm_sm_dual<<<dim3(1, 16, BATCH), 128>>>(tA, tB, 8);     // A+B
    rvec_kernel<<<BATCH, 64>>>(zf_t, bq, r);                  // C
    gemm_sm_dual<<<dim3(1, 16, BATCH), 128>>>(tD, tE, 8);     // D+E
    gemm_simG_kernel<<<dim3(1, 31, BATCH), 128>>>(xf, tp, r, simT);  // G+H fused

    // ---- join: I needs xf_g (s2) + simT/u (main) ----
    cudaStreamWaitEvent(0, evJoinF, 0);
    gemm128f_kernel<<<dim3(8, 2, BATCH), blk>>>(
        u, sU, UPAD,  Wfi + CC, 0, 2 * CC,
        simT, sST, NX,  xf_g, sX, NX,  UPAD,
        gat, sX, NX,  CC, NX, UPAD + CC,  bfi, 1,
        fi_gamma, fi_beta, fi_mean, fi_var);

    // ---- fork: J (transpose + colcnt zero) on s2, parallel with K, L ----
    cudaEventRecord(evForkJ, 0);
    cudaStreamWaitEvent(s2, evForkJ, 0);
    transpose_kernel<<<dim3(31, 8, BATCH), dim3(32, 8), 0, s2>>>(gat, gatT, colcnt);
    cudaEventRecord(evJoinJ, s2);

    // K) e = prelu(bn(conv3x3(gat) + bm))
    conv3_kernel<<<dim3(BATCH, CM / OCB), blk>>>(
        gat, Wm, bm, m_gamma, m_beta, m_mean, m_var, prelu_a, e);
    // L) S = e^T e, symmetric
    gemm_symL_kernel<<<dim3(36, 1, BATCH), blk>>>(e, S);

    // ---- join: M needs colcnt (s2) + S (main) ----
    cudaStreamWaitEvent(0, evJoinJ, 0);
    sparsemax_scatter_kernel<<<(BATCH * NX + 7) / 8, blk>>>(
        S, colpk, colcnt, BATCH * NX);
    sparse_out_kernel<<<dim3((NX + MCOLS - 1) / MCOLS, BATCH), blk>>>(
        gatT, colpk, colcnt, out);
}